// round 7
// baseline (speedup 1.0000x reference)
#include <cuda_runtime.h>
#include <cuda_bf16.h>
#include <cstdint>
#include <math.h>

// Problem constants
#define BB   2
#define TT   2048
#define DD   2048
#define HH   32
#define KVH  8
#define HD   64
#define MTOT (BB*TT)      // 4096
#define DKV  (KVH*HD)     // 512

// ---------------------------------------------------------------------------
// Scratch (__device__ globals; no allocation allowed) — all split bf16 pairs
// ---------------------------------------------------------------------------
__device__ __nv_bfloat16 g_xhi[(size_t)MTOT * DD],  g_xlo[(size_t)MTOT * DD];
__device__ __nv_bfloat16 g_Wqhi[(size_t)DD * DD],   g_Wqlo[(size_t)DD * DD];
__device__ __nv_bfloat16 g_Wkhi[(size_t)DKV * DD],  g_Wklo[(size_t)DKV * DD];
__device__ __nv_bfloat16 g_Wvhi[(size_t)DKV * DD],  g_Wvlo[(size_t)DKV * DD];
__device__ __nv_bfloat16 g_Wohi[(size_t)DD * DD],   g_Wolo[(size_t)DD * DD];

__device__ __nv_bfloat16 g_Qhi[(size_t)MTOT * DD],  g_Qlo[(size_t)MTOT * DD];
__device__ __nv_bfloat16 g_Khi[(size_t)MTOT * DKV], g_Klo[(size_t)MTOT * DKV];
__device__ __nv_bfloat16 g_Vhi[(size_t)MTOT * DKV], g_Vlo[(size_t)MTOT * DKV];
__device__ __nv_bfloat16 g_Ahi[(size_t)MTOT * DD],  g_Alo[(size_t)MTOT * DD];

// ---------------------------------------------------------------------------
// Helpers (portable PTX only: cp.async / ldmatrix / mma.sync)
// ---------------------------------------------------------------------------
__device__ __forceinline__ uint32_t s2u(const void* p) {
    return (uint32_t)__cvta_generic_to_shared(p);
}

#define CP16(sa, ga) \
    asm volatile("cp.async.cg.shared.global [%0], [%1], 16;" :: "r"(sa), "l"(ga) : "memory")
#define CPCOMMIT()  asm volatile("cp.async.commit_group;" ::: "memory")
#define CPWAIT(n)   asm volatile("cp.async.wait_group %0;" :: "n"(n) : "memory")

#define LDSM4(r0, r1, r2, r3, addr) \
    asm volatile("ldmatrix.sync.aligned.m8n8.x4.shared.b16 {%0,%1,%2,%3}, [%4];" \
        : "=r"(r0), "=r"(r1), "=r"(r2), "=r"(r3) : "r"(addr))

#define LDSM4T(r0, r1, r2, r3, addr) \
    asm volatile("ldmatrix.sync.aligned.m8n8.x4.trans.shared.b16 {%0,%1,%2,%3}, [%4];" \
        : "=r"(r0), "=r"(r1), "=r"(r2), "=r"(r3) : "r"(addr))

#define MMA16816(d, a, b) \
    asm volatile("mma.sync.aligned.m16n8k16.row.col.f32.bf16.bf16.f32 " \
        "{%0,%1,%2,%3}, {%4,%5,%6,%7}, {%8,%9}, {%0,%1,%2,%3};" \
        : "+f"((d)[0]), "+f"((d)[1]), "+f"((d)[2]), "+f"((d)[3]) \
        : "r"((a)[0]), "r"((a)[1]), "r"((a)[2]), "r"((a)[3]), "r"((b)[0]), "r"((b)[1]))

#define MMA16816R(d, a, b0v, b1v) \
    asm volatile("mma.sync.aligned.m16n8k16.row.col.f32.bf16.bf16.f32 " \
        "{%0,%1,%2,%3}, {%4,%5,%6,%7}, {%8,%9}, {%0,%1,%2,%3};" \
        : "+f"((d)[0]), "+f"((d)[1]), "+f"((d)[2]), "+f"((d)[3]) \
        : "r"((a)[0]), "r"((a)[1]), "r"((a)[2]), "r"((a)[3]), "r"(b0v), "r"(b1v))

// 64B-row swizzle (GEMM tiles)
__device__ __forceinline__ uint32_t sw_addr(uint32_t base, int row, int chunk) {
    return base + row * 64 + ((chunk ^ ((row >> 1) & 3)) << 4);
}
// 128B-row swizzle (flash tiles)
__device__ __forceinline__ uint32_t sw128(uint32_t base, int row, int chunk) {
    return base + row * 128 + ((chunk ^ (row & 7)) << 4);
}

// split fp32 pair -> packed bf16x2 (hi, lo)
__device__ __forceinline__ void pack_split(float x0, float x1, uint32_t& hi, uint32_t& lo) {
    __nv_bfloat16 h0 = __float2bfloat16(x0);
    __nv_bfloat16 h1 = __float2bfloat16(x1);
    __nv_bfloat16 l0 = __float2bfloat16(x0 - __bfloat162float(h0));
    __nv_bfloat16 l1 = __float2bfloat16(x1 - __bfloat162float(h1));
    __nv_bfloat162 hp(h0, h1), lp(l0, l1);
    hi = *(uint32_t*)&hp;
    lo = *(uint32_t*)&lp;
}

// ---------------------------------------------------------------------------
// fp32 -> (bf16 hi, bf16 lo) split kernel (inputs only)
// ---------------------------------------------------------------------------
__global__ __launch_bounds__(256)
void split_kernel(const float* __restrict__ src, __nv_bfloat16* __restrict__ hi,
                  __nv_bfloat16* __restrict__ lo, int n4)
{
    int i = blockIdx.x * blockDim.x + threadIdx.x;
    if (i >= n4) return;
    float4 v = ((const float4*)src)[i];
    uint32_t h0, l0, h1, l1;
    pack_split(v.x, v.y, h0, l0);
    pack_split(v.z, v.w, h1, l1);
    ((uint2*)hi)[i] = make_uint2(h0, h1);
    ((uint2*)lo)[i] = make_uint2(l0, l1);
}

// ---------------------------------------------------------------------------
// mma.sync GEMM:  C = A * B^T  (3-pass bf16 split precision)
// CTA 128x128, BK=32, 4-stage cp.async, ONE __syncthreads per chunk.
// 512 threads = 16 warps (4x4 grid), warp tile 32x32. 4 warps/SMSP.
// ---------------------------------------------------------------------------
#define STAGES      4
#define TILE_B      8192
#define STAGE_B     (4 * TILE_B)            // 32 KB
#define GEMM_SMEM   (STAGES * STAGE_B)      // 128 KB

template<bool SPLIT>
__global__ __launch_bounds__(512)
void gemm_tc_kernel(const __nv_bfloat16* __restrict__ Ahi, const __nv_bfloat16* __restrict__ Alo,
                    const __nv_bfloat16* __restrict__ Bhi, const __nv_bfloat16* __restrict__ Blo,
                    float* __restrict__ C,
                    __nv_bfloat16* __restrict__ Chi, __nv_bfloat16* __restrict__ Clo,
                    int M, int N, int K)
{
    extern __shared__ __align__(128) char smem[];
    const uint32_t sbase = s2u(smem);

    const int tid = threadIdx.x;
    const int wid = tid >> 5;
    const int lane = tid & 31;
    const int bm = blockIdx.y * 128;
    const int bn = blockIdx.x * 128;

    const int wm = (wid & 3) * 32;      // warp M offset (4 warps in M)
    const int wn = (wid >> 2) * 32;     // warp N offset (4 warps in N)

    const char* srcs[4] = {(const char*)Ahi, (const char*)Alo,
                           (const char*)Bhi, (const char*)Blo};
    const size_t rowstride = (size_t)K * 2;

    const int NC = K >> 5;

    auto load_chunk = [&](int c, int s) {
        const uint32_t sb = sbase + s * STAGE_B;
        const size_t k0b = (size_t)c * 64;
#pragma unroll
        for (int t = 0; t < 4; t++) {
            const int rbase = (t < 2) ? bm : bn;
            const char* src = srcs[t];
            int r = tid >> 2;               // 0..127
            int ck = tid & 3;               // 16B chunk
            const char* ga = src + (size_t)(rbase + r) * rowstride + k0b + ck * 16;
            CP16(sw_addr(sb + t * TILE_B, r, ck), ga);
        }
    };

    float acc[2][4][4];
#pragma unroll
    for (int i = 0; i < 2; i++)
#pragma unroll
        for (int j = 0; j < 4; j++)
#pragma unroll
            for (int q = 0; q < 4; q++) acc[i][j][q] = 0.f;

    // prefill 3 stages (NC >= 16 always here)
    load_chunk(0, 0); CPCOMMIT();
    load_chunk(1, 1); CPCOMMIT();
    load_chunk(2, 2); CPCOMMIT();

    for (int c = 0; c < NC; c++) {
        const int s = c & 3;
        CPWAIT(2);                 // chunk c resident (pending: c+1, c+2)
        __syncthreads();           // single barrier per chunk

        if (c + 3 < NC) {          // overwrites stage (c-1)&3 — reads done pre-barrier
            load_chunk(c + 3, (c + 3) & 3);
            CPCOMMIT();
        }

        const uint32_t sb   = sbase + s * STAGE_B;
        const uint32_t sAhi = sb;
        const uint32_t sAlo = sb + TILE_B;
        const uint32_t sBhi = sb + 2 * TILE_B;
        const uint32_t sBlo = sb + 3 * TILE_B;

#pragma unroll
        for (int ks = 0; ks < 2; ks++) {
            const int ckbase = ks * 2;

            uint32_t ahi[2][4], alo[2][4], bhi[4][2], blo[4][2];
            {
                int ar = (lane & 15);
                int ac = ckbase + (lane >> 4);
#pragma unroll
                for (int fm = 0; fm < 2; fm++) {
                    uint32_t ad = sw_addr(sAhi, wm + fm * 16 + ar, ac);
                    LDSM4(ahi[fm][0], ahi[fm][1], ahi[fm][2], ahi[fm][3], ad);
                    uint32_t ad2 = sw_addr(sAlo, wm + fm * 16 + ar, ac);
                    LDSM4(alo[fm][0], alo[fm][1], alo[fm][2], alo[fm][3], ad2);
                }
                int br = (lane & 7);
                int bsel = (lane >> 4);
                int bc = ckbase + ((lane >> 3) & 1);
#pragma unroll
                for (int fp = 0; fp < 2; fp++) {
                    uint32_t bd = sw_addr(sBhi, wn + (fp * 2 + bsel) * 8 + br, bc);
                    uint32_t t0, t1, t2, t3;
                    LDSM4(t0, t1, t2, t3, bd);
                    bhi[fp * 2][0] = t0; bhi[fp * 2][1] = t1;
                    bhi[fp * 2 + 1][0] = t2; bhi[fp * 2 + 1][1] = t3;
                    uint32_t bd2 = sw_addr(sBlo, wn + (fp * 2 + bsel) * 8 + br, bc);
                    LDSM4(t0, t1, t2, t3, bd2);
                    blo[fp * 2][0] = t0; blo[fp * 2][1] = t1;
                    blo[fp * 2 + 1][0] = t2; blo[fp * 2 + 1][1] = t3;
                }
            }

#pragma unroll
            for (int fm = 0; fm < 2; fm++)
#pragma unroll
                for (int fn = 0; fn < 4; fn++) {
                    MMA16816(acc[fm][fn], ahi[fm], bhi[fn]);
                    MMA16816(acc[fm][fn], alo[fm], bhi[fn]);
                    MMA16816(acc[fm][fn], ahi[fm], blo[fn]);
                }
        }
        // no trailing barrier: next iteration's top barrier closes the hazard
    }

    const int lr = lane >> 2;
    const int lc = (lane & 3) * 2;
#pragma unroll
    for (int fm = 0; fm < 2; fm++) {
#pragma unroll
        for (int fn = 0; fn < 4; fn++) {
            int r0 = bm + wm + fm * 16 + lr;
            int cc = bn + wn + fn * 8 + lc;
            if (SPLIT) {
                uint32_t h, l;
                pack_split(acc[fm][fn][0], acc[fm][fn][1], h, l);
                *(uint32_t*)&Chi[(size_t)r0 * N + cc] = h;
                *(uint32_t*)&Clo[(size_t)r0 * N + cc] = l;
                pack_split(acc[fm][fn][2], acc[fm][fn][3], h, l);
                *(uint32_t*)&Chi[(size_t)(r0 + 8) * N + cc] = h;
                *(uint32_t*)&Clo[(size_t)(r0 + 8) * N + cc] = l;
            } else {
                *(float2*)&C[(size_t)r0 * N + cc]       = make_float2(acc[fm][fn][0], acc[fm][fn][1]);
                *(float2*)&C[(size_t)(r0 + 8) * N + cc] = make_float2(acc[fm][fn][2], acc[fm][fn][3]);
            }
        }
    }
}

// ---------------------------------------------------------------------------
// Tensor-core flash attention (split-precision bf16 mma) — unchanged from R6.
// Grid (T/128, H, B), 256 threads = 8 warps x 16 q-rows.
// KV tile 64, 3-stage cp.async ring, ONE __syncthreads per KV tile.
// ---------------------------------------------------------------------------
#define QTILE_B   16384
#define KVSUB_B   8192
#define FSTAGE_B  (4 * KVSUB_B)
#define FSTAGES   3
#define FLASH_SMEM (2 * QTILE_B + FSTAGES * FSTAGE_B)

__global__ __launch_bounds__(256, 1)
void flash_tc_kernel()
{
    extern __shared__ __align__(128) char fsm[];
    const uint32_t sbase = s2u(fsm);
    const uint32_t QHI = sbase;
    const uint32_t QLO = sbase + QTILE_B;
    const uint32_t STG0 = sbase + 2 * QTILE_B;

    const int qt  = blockIdx.x;
    const int h   = blockIdx.y;
    const int b   = blockIdx.z;
    const int kvh = h >> 2;
    const int qb  = qt * 128;

    const int tid = threadIdx.x;
    const int wid = tid >> 5;
    const int lane = tid & 31;

#pragma unroll
    for (int j = 0; j < 4; j++) {
        int i = tid + j * 256;
        int r = i >> 3;
        int ck = i & 7;
        size_t e = (size_t)(b * TT + qb + r) * DD + h * HD + ck * 8;
        CP16(sw128(QHI, r, ck), (const char*)&g_Qhi[e]);
        CP16(sw128(QLO, r, ck), (const char*)&g_Qlo[e]);
    }
    CPCOMMIT();

    auto load_kv = [&](int kt, int s) {
        const uint32_t sb = STG0 + s * FSTAGE_B;
#pragma unroll
        for (int j = 0; j < 2; j++) {
            int i = tid + j * 256;
            int r = i >> 3;
            int ck = i & 7;
            size_t e = (size_t)(b * TT + kt * 64 + r) * DKV + kvh * HD + ck * 8;
            uint32_t so = sw128(sb, r, ck);
            CP16(so,               (const char*)&g_Khi[e]);
            CP16(so + KVSUB_B,     (const char*)&g_Klo[e]);
            CP16(so + 2 * KVSUB_B, (const char*)&g_Vhi[e]);
            CP16(so + 3 * KVSUB_B, (const char*)&g_Vlo[e]);
        }
    };

    const int NT = 2 * (qt + 1);

    load_kv(0, 0); CPCOMMIT();
    if (NT > 1) { load_kv(1, 1); CPCOMMIT(); }

    CPWAIT(2);
    __syncthreads();

    uint32_t qhiF[4][4], qloF[4][4];
    {
        int ar = lane & 15;
        int ac = lane >> 4;
#pragma unroll
        for (int ks = 0; ks < 4; ks++) {
            uint32_t ad = sw128(QHI, wid * 16 + ar, 2 * ks + ac);
            LDSM4(qhiF[ks][0], qhiF[ks][1], qhiF[ks][2], qhiF[ks][3], ad);
            uint32_t ad2 = sw128(QLO, wid * 16 + ar, 2 * ks + ac);
            LDSM4(qloF[ks][0], qloF[ks][1], qloF[ks][2], qloF[ks][3], ad2);
        }
    }

    float oacc[8][4];
#pragma unroll
    for (int i = 0; i < 8; i++)
#pragma unroll
        for (int q = 0; q < 4; q++) oacc[i][q] = 0.f;
    float mrow[2] = {-1e30f, -1e30f};
    float lrow[2] = {0.f, 0.f};

    const int wr = qb + wid * 16;
    const float scale = 0.125f;

    for (int kt = 0; kt < NT; kt++) {
        const int s = kt % FSTAGES;
        const int kb = kt * 64;

        CPWAIT(1);
        __syncthreads();

        if (kt + 2 < NT) {
            load_kv(kt + 2, (kt + 2) % FSTAGES);
            CPCOMMIT();
        }

        const uint32_t KH = STG0 + s * FSTAGE_B;
        const uint32_t KL = KH + KVSUB_B;
        const uint32_t VH = KH + 2 * KVSUB_B;
        const uint32_t VL = KH + 3 * KVSUB_B;

        float sacc[8][4];
#pragma unroll
        for (int i = 0; i < 8; i++)
#pragma unroll
            for (int q = 0; q < 4; q++) sacc[i][q] = 0.f;

        {
            int br = lane & 7;
            int bsel = lane >> 4;
            int bksel = (lane >> 3) & 1;
#pragma unroll
            for (int ks = 0; ks < 4; ks++) {
                int bc = 2 * ks + bksel;
#pragma unroll
                for (int fp = 0; fp < 4; fp++) {
                    int krow = fp * 16 + bsel * 8 + br;
                    uint32_t t0, t1, t2, t3, u0, u1, u2, u3;
                    LDSM4(t0, t1, t2, t3, sw128(KH, krow, bc));
                    LDSM4(u0, u1, u2, u3, sw128(KL, krow, bc));
                    MMA16816R(sacc[2 * fp],     qhiF[ks], t0, t1);
                    MMA16816R(sacc[2 * fp],     qloF[ks], t0, t1);
                    MMA16816R(sacc[2 * fp],     qhiF[ks], u0, u1);
                    MMA16816R(sacc[2 * fp + 1], qhiF[ks], t2, t3);
                    MMA16816R(sacc[2 * fp + 1], qloF[ks], t2, t3);
                    MMA16816R(sacc[2 * fp + 1], qhiF[ks], u2, u3);
                }
            }
        }

        const bool need_mask = (kb + 63 > wr);
#pragma unroll
        for (int fn = 0; fn < 8; fn++)
#pragma unroll
            for (int q = 0; q < 4; q++) sacc[fn][q] *= scale;
        if (need_mask) {
#pragma unroll
            for (int fn = 0; fn < 8; fn++)
#pragma unroll
                for (int q = 0; q < 4; q++) {
                    int kc = kb + fn * 8 + (lane & 3) * 2 + (q & 1);
                    int qr = wr + (lane >> 2) + (q >> 1) * 8;
                    if (kc > qr) sacc[fn][q] = -1e30f;
                }
        }

#pragma unroll
        for (int r = 0; r < 2; r++) {
            float rmax = -1e30f;
#pragma unroll
            for (int fn = 0; fn < 8; fn++) {
                rmax = fmaxf(rmax, sacc[fn][2 * r]);
                rmax = fmaxf(rmax, sacc[fn][2 * r + 1]);
            }
            rmax = fmaxf(rmax, __shfl_xor_sync(0xffffffffu, rmax, 1));
            rmax = fmaxf(rmax, __shfl_xor_sync(0xffffffffu, rmax, 2));

            float mn = fmaxf(mrow[r], rmax);
            float alpha = __expf(mrow[r] - mn);
            mrow[r] = mn;

            float rs = 0.f;
#pragma unroll
            for (int fn = 0; fn < 8; fn++) {
                float p0 = __expf(sacc[fn][2 * r] - mn);
                float p1 = __expf(sacc[fn][2 * r + 1] - mn);
                sacc[fn][2 * r] = p0;
                sacc[fn][2 * r + 1] = p1;
                rs += p0 + p1;
            }
            rs += __shfl_xor_sync(0xffffffffu, rs, 1);
            rs += __shfl_xor_sync(0xffffffffu, rs, 2);
            lrow[r] = lrow[r] * alpha + rs;

#pragma unroll
            for (int fn = 0; fn < 8; fn++) {
                oacc[fn][2 * r]     *= alpha;
                oacc[fn][2 * r + 1] *= alpha;
            }
        }

        {
            int g = lane >> 3;
            int vr_off = (g & 1) * 8 + (lane & 7);
            int vc_off = g >> 1;
#pragma unroll
            for (int ks = 0; ks < 4; ks++) {
                uint32_t phiF[4], ploF[4];
                pack_split(sacc[2 * ks][0],     sacc[2 * ks][1],     phiF[0], ploF[0]);
                pack_split(sacc[2 * ks][2],     sacc[2 * ks][3],     phiF[1], ploF[1]);
                pack_split(sacc[2 * ks + 1][0], sacc[2 * ks + 1][1], phiF[2], ploF[2]);
                pack_split(sacc[2 * ks + 1][2], sacc[2 * ks + 1][3], phiF[3], ploF[3]);

                int vrow = ks * 16 + vr_off;
#pragma unroll
                for (int fv = 0; fv < 4; fv++) {
                    int vchunk = 2 * fv + vc_off;
                    uint32_t t0, t1, t2, t3, u0, u1, u2, u3;
                    LDSM4T(t0, t1, t2, t3, sw128(VH, vrow, vchunk));
                    LDSM4T(u0, u1, u2, u3, sw128(VL, vrow, vchunk));
                    MMA16816R(oacc[2 * fv],     phiF, t0, t1);
                    MMA16816R(oacc[2 * fv],     ploF, t0, t1);
                    MMA16816R(oacc[2 * fv],     phiF, u0, u1);
                    MMA16816R(oacc[2 * fv + 1], phiF, t2, t3);
                    MMA16816R(oacc[2 * fv + 1], ploF, t2, t3);
                    MMA16816R(oacc[2 * fv + 1], phiF, u2, u3);
                }
            }
        }
    }

#pragma unroll
    for (int r = 0; r < 2; r++) {
        float inv = 1.f / lrow[r];
        int row = wr + (lane >> 2) + 8 * r;
#pragma unroll
        for (int fn = 0; fn < 8; fn++) {
            int col = h * HD + fn * 8 + (lane & 3) * 2;
            float x0 = oacc[fn][2 * r] * inv;
            float x1 = oacc[fn][2 * r + 1] * inv;
            uint32_t hv, lv;
            pack_split(x0, x1, hv, lv);
            size_t e = (size_t)(b * TT + row) * DD + col;
            *(uint32_t*)&g_Ahi[e] = hv;
            *(uint32_t*)&g_Alo[e] = lv;
        }
    }
}

// ---------------------------------------------------------------------------
// Launch
// ---------------------------------------------------------------------------
extern "C" void kernel_launch(void* const* d_in, const int* in_sizes, int n_in,
                              void* d_out, int out_size)
{
    const float* x  = (const float*)d_in[0];
    const float* Wq = (const float*)d_in[1];
    const float* Wk = (const float*)d_in[2];
    const float* Wv = (const float*)d_in[3];
    const float* Wo = (const float*)d_in[4];
    float* out = (float*)d_out;

    __nv_bfloat16 *xh, *xl, *wqh, *wql, *wkh, *wkl, *wvh, *wvl, *woh, *wol;
    __nv_bfloat16 *qh, *ql, *kh, *kl, *vh, *vl, *ah, *al;
    cudaGetSymbolAddress((void**)&xh, g_xhi);   cudaGetSymbolAddress((void**)&xl, g_xlo);
    cudaGetSymbolAddress((void**)&wqh, g_Wqhi); cudaGetSymbolAddress((void**)&wql, g_Wqlo);
    cudaGetSymbolAddress((void**)&wkh, g_Wkhi); cudaGetSymbolAddress((void**)&wkl, g_Wklo);
    cudaGetSymbolAddress((void**)&wvh, g_Wvhi); cudaGetSymbolAddress((void**)&wvl, g_Wvlo);
    cudaGetSymbolAddress((void**)&woh, g_Wohi); cudaGetSymbolAddress((void**)&wol, g_Wolo);
    cudaGetSymbolAddress((void**)&qh, g_Qhi);   cudaGetSymbolAddress((void**)&ql, g_Qlo);
    cudaGetSymbolAddress((void**)&kh, g_Khi);   cudaGetSymbolAddress((void**)&kl, g_Klo);
    cudaGetSymbolAddress((void**)&vh, g_Vhi);   cudaGetSymbolAddress((void**)&vl, g_Vlo);
    cudaGetSymbolAddress((void**)&ah, g_Ahi);   cudaGetSymbolAddress((void**)&al, g_Alo);

    cudaFuncSetAttribute(gemm_tc_kernel<true>,
                         cudaFuncAttributeMaxDynamicSharedMemorySize, GEMM_SMEM);
    cudaFuncSetAttribute(gemm_tc_kernel<false>,
                         cudaFuncAttributeMaxDynamicSharedMemorySize, GEMM_SMEM);
    cudaFuncSetAttribute(flash_tc_kernel,
                         cudaFuncAttributeMaxDynamicSharedMemorySize, FLASH_SMEM);

    // fp32 -> bf16 hi/lo splits (inputs only)
    const int n_x  = MTOT * DD / 4, n_wq = DD * DD / 4, n_wk = DKV * DD / 4;
    split_kernel<<<(n_x  + 255) / 256, 256>>>(x,  xh,  xl,  n_x);
    split_kernel<<<(n_wq + 255) / 256, 256>>>(Wq, wqh, wql, n_wq);
    split_kernel<<<(n_wk + 255) / 256, 256>>>(Wk, wkh, wkl, n_wk);
    split_kernel<<<(n_wk + 255) / 256, 256>>>(Wv, wvh, wvl, n_wk);
    split_kernel<<<(n_wq + 255) / 256, 256>>>(Wo, woh, wol, n_wq);

    // Projections -> split bf16 outputs
    gemm_tc_kernel<true><<<dim3(DD / 128, MTOT / 128), 512, GEMM_SMEM>>>(
        xh, xl, wqh, wql, nullptr, qh, ql, MTOT, DD, DD);
    gemm_tc_kernel<true><<<dim3(DKV / 128, MTOT / 128), 512, GEMM_SMEM>>>(
        xh, xl, wkh, wkl, nullptr, kh, kl, MTOT, DKV, DD);
    gemm_tc_kernel<true><<<dim3(DKV / 128, MTOT / 128), 512, GEMM_SMEM>>>(
        xh, xl, wvh, wvl, nullptr, vh, vl, MTOT, DKV, DD);

    // Tensor-core causal GQA flash attention -> split bf16 A
    flash_tc_kernel<<<dim3(TT / 128, HH, BB), 256, FLASH_SMEM>>>();

    // Output projection -> fp32 out
    gemm_tc_kernel<false><<<dim3(DD / 128, MTOT / 128), 512, GEMM_SMEM>>>(
        ah, al, woh, wol, out, nullptr, nullptr, MTOT, DD, DD);
}

// round 8
// speedup vs baseline: 1.2242x; 1.2242x over previous
#include <cuda_runtime.h>
#include <cuda_bf16.h>
#include <cuda_fp16.h>
#include <cstdint>
#include <math.h>

// Problem constants
#define BB   2
#define TT   2048
#define DD   2048
#define HH   32
#define KVH  8
#define HD   64
#define MTOT (BB*TT)      // 4096
#define DKV  (KVH*HD)     // 512

// ---------------------------------------------------------------------------
// Scratch (__device__ globals; no allocation allowed)
// ---------------------------------------------------------------------------
__device__ __half g_xhi[(size_t)MTOT * DD], g_xlo[(size_t)MTOT * DD];   // fp16 split x
__device__ __half g_Wq[(size_t)DD * DD];                                 // fp16 weights
__device__ __half g_Wk[(size_t)DKV * DD];
__device__ __half g_Wv[(size_t)DKV * DD];
__device__ __half g_Wo[(size_t)DD * DD];

__device__ __nv_bfloat16 g_Qhi[(size_t)MTOT * DD],  g_Qlo[(size_t)MTOT * DD];
__device__ __nv_bfloat16 g_Khi[(size_t)MTOT * DKV], g_Klo[(size_t)MTOT * DKV];
__device__ __nv_bfloat16 g_Vhi[(size_t)MTOT * DKV], g_Vlo[(size_t)MTOT * DKV];
__device__ __half g_Ahi[(size_t)MTOT * DD], g_Alo[(size_t)MTOT * DD];   // fp16 split attn out

// ---------------------------------------------------------------------------
// Helpers (portable PTX only: cp.async / ldmatrix / mma.sync)
// ---------------------------------------------------------------------------
__device__ __forceinline__ uint32_t s2u(const void* p) {
    return (uint32_t)__cvta_generic_to_shared(p);
}

#define CP16(sa, ga) \
    asm volatile("cp.async.cg.shared.global [%0], [%1], 16;" :: "r"(sa), "l"(ga) : "memory")
#define CPCOMMIT()  asm volatile("cp.async.commit_group;" ::: "memory")
#define CPWAIT(n)   asm volatile("cp.async.wait_group %0;" :: "n"(n) : "memory")

#define LDSM4(r0, r1, r2, r3, addr) \
    asm volatile("ldmatrix.sync.aligned.m8n8.x4.shared.b16 {%0,%1,%2,%3}, [%4];" \
        : "=r"(r0), "=r"(r1), "=r"(r2), "=r"(r3) : "r"(addr))

#define LDSM4T(r0, r1, r2, r3, addr) \
    asm volatile("ldmatrix.sync.aligned.m8n8.x4.trans.shared.b16 {%0,%1,%2,%3}, [%4];" \
        : "=r"(r0), "=r"(r1), "=r"(r2), "=r"(r3) : "r"(addr))

// bf16 mma
#define MMA16816(d, a, b) \
    asm volatile("mma.sync.aligned.m16n8k16.row.col.f32.bf16.bf16.f32 " \
        "{%0,%1,%2,%3}, {%4,%5,%6,%7}, {%8,%9}, {%0,%1,%2,%3};" \
        : "+f"((d)[0]), "+f"((d)[1]), "+f"((d)[2]), "+f"((d)[3]) \
        : "r"((a)[0]), "r"((a)[1]), "r"((a)[2]), "r"((a)[3]), "r"((b)[0]), "r"((b)[1]))

#define MMA16816R(d, a, b0v, b1v) \
    asm volatile("mma.sync.aligned.m16n8k16.row.col.f32.bf16.bf16.f32 " \
        "{%0,%1,%2,%3}, {%4,%5,%6,%7}, {%8,%9}, {%0,%1,%2,%3};" \
        : "+f"((d)[0]), "+f"((d)[1]), "+f"((d)[2]), "+f"((d)[3]) \
        : "r"((a)[0]), "r"((a)[1]), "r"((a)[2]), "r"((a)[3]), "r"(b0v), "r"(b1v))

// fp16 mma
#define MMAH16816(d, a, b) \
    asm volatile("mma.sync.aligned.m16n8k16.row.col.f32.f16.f16.f32 " \
        "{%0,%1,%2,%3}, {%4,%5,%6,%7}, {%8,%9}, {%0,%1,%2,%3};" \
        : "+f"((d)[0]), "+f"((d)[1]), "+f"((d)[2]), "+f"((d)[3]) \
        : "r"((a)[0]), "r"((a)[1]), "r"((a)[2]), "r"((a)[3]), "r"((b)[0]), "r"((b)[1]))

// 64B-row swizzle (GEMM tiles)
__device__ __forceinline__ uint32_t sw_addr(uint32_t base, int row, int chunk) {
    return base + row * 64 + ((chunk ^ ((row >> 1) & 3)) << 4);
}
// 128B-row swizzle (flash tiles)
__device__ __forceinline__ uint32_t sw128(uint32_t base, int row, int chunk) {
    return base + row * 128 + ((chunk ^ (row & 7)) << 4);
}

// fp32 pair -> packed bf16x2 hi/lo
__device__ __forceinline__ void pack_split(float x0, float x1, uint32_t& hi, uint32_t& lo) {
    __nv_bfloat16 h0 = __float2bfloat16(x0);
    __nv_bfloat16 h1 = __float2bfloat16(x1);
    __nv_bfloat16 l0 = __float2bfloat16(x0 - __bfloat162float(h0));
    __nv_bfloat16 l1 = __float2bfloat16(x1 - __bfloat162float(h1));
    __nv_bfloat162 hp(h0, h1), lp(l0, l1);
    hi = *(uint32_t*)&hp;
    lo = *(uint32_t*)&lp;
}

// fp32 pair -> packed fp16x2 hi/lo
__device__ __forceinline__ void pack_split_h(float x0, float x1, uint32_t& hi, uint32_t& lo) {
    __half h0 = __float2half_rn(x0);
    __half h1 = __float2half_rn(x1);
    __half l0 = __float2half_rn(x0 - __half2float(h0));
    __half l1 = __float2half_rn(x1 - __half2float(h1));
    __half2 hp = __halves2half2(h0, h1), lp = __halves2half2(l0, l1);
    hi = *(uint32_t*)&hp;
    lo = *(uint32_t*)&lp;
}

// ---------------------------------------------------------------------------
// fp32 -> fp16 hi/lo split kernel (x)
// ---------------------------------------------------------------------------
__global__ __launch_bounds__(256)
void split_h_kernel(const float* __restrict__ src, __half* __restrict__ hi,
                    __half* __restrict__ lo, int n4)
{
    int i = blockIdx.x * blockDim.x + threadIdx.x;
    if (i >= n4) return;
    float4 v = ((const float4*)src)[i];
    uint32_t h0, l0, h1, l1;
    pack_split_h(v.x, v.y, h0, l0);
    pack_split_h(v.z, v.w, h1, l1);
    ((uint2*)hi)[i] = make_uint2(h0, h1);
    ((uint2*)lo)[i] = make_uint2(l0, l1);
}

// fp32 -> fp16 convert kernel (weights)
__global__ __launch_bounds__(256)
void conv_h_kernel(const float* __restrict__ src, __half* __restrict__ dst, int n4)
{
    int i = blockIdx.x * blockDim.x + threadIdx.x;
    if (i >= n4) return;
    float4 v = ((const float4*)src)[i];
    __half2 p0 = __halves2half2(__float2half_rn(v.x), __float2half_rn(v.y));
    __half2 p1 = __halves2half2(__float2half_rn(v.z), __float2half_rn(v.w));
    ((uint2*)dst)[i] = make_uint2(*(uint32_t*)&p0, *(uint32_t*)&p1);
}

// ---------------------------------------------------------------------------
// fp16 2-pass GEMM:  C = (Ahi+Alo) * Bh^T   (B is fp16 hi-only)
// CTA 128x128, BK=32, 4-stage cp.async, one __syncthreads per chunk.
// 512 threads = 16 warps (4x4), warp tile 32x32.
// Stage = 3 tiles (Ahi,Alo,Bh) x 8KB = 24KB; 4 stages = 96KB.
// ---------------------------------------------------------------------------
#define STAGES      4
#define TILE_B      8192
#define STAGE_B     (3 * TILE_B)            // 24 KB
#define GEMM_SMEM   (STAGES * STAGE_B)      // 96 KB

template<bool SPLIT>
__global__ __launch_bounds__(512)
void gemm_tc_kernel(const __half* __restrict__ Ahi, const __half* __restrict__ Alo,
                    const __half* __restrict__ Bh,
                    float* __restrict__ C,
                    __nv_bfloat16* __restrict__ Chi, __nv_bfloat16* __restrict__ Clo,
                    int M, int N, int K)
{
    extern __shared__ __align__(128) char smem[];
    const uint32_t sbase = s2u(smem);

    const int tid = threadIdx.x;
    const int wid = tid >> 5;
    const int lane = tid & 31;
    const int bm = blockIdx.y * 128;
    const int bn = blockIdx.x * 128;

    const int wm = (wid & 3) * 32;
    const int wn = (wid >> 2) * 32;

    const char* srcs[3] = {(const char*)Ahi, (const char*)Alo, (const char*)Bh};
    const size_t rowstride = (size_t)K * 2;

    const int NC = K >> 5;

    auto load_chunk = [&](int c, int s) {
        const uint32_t sb = sbase + s * STAGE_B;
        const size_t k0b = (size_t)c * 64;
#pragma unroll
        for (int t = 0; t < 3; t++) {
            const int rbase = (t < 2) ? bm : bn;
            const char* src = srcs[t];
            int r = tid >> 2;
            int ck = tid & 3;
            const char* ga = src + (size_t)(rbase + r) * rowstride + k0b + ck * 16;
            CP16(sw_addr(sb + t * TILE_B, r, ck), ga);
        }
    };

    float acc[2][4][4];
#pragma unroll
    for (int i = 0; i < 2; i++)
#pragma unroll
        for (int j = 0; j < 4; j++)
#pragma unroll
            for (int q = 0; q < 4; q++) acc[i][j][q] = 0.f;

    load_chunk(0, 0); CPCOMMIT();
    load_chunk(1, 1); CPCOMMIT();
    load_chunk(2, 2); CPCOMMIT();

    for (int c = 0; c < NC; c++) {
        const int s = c & 3;
        CPWAIT(2);
        __syncthreads();

        if (c + 3 < NC) {
            load_chunk(c + 3, (c + 3) & 3);
            CPCOMMIT();
        }

        const uint32_t sb   = sbase + s * STAGE_B;
        const uint32_t sAhi = sb;
        const uint32_t sAlo = sb + TILE_B;
        const uint32_t sBh  = sb + 2 * TILE_B;

#pragma unroll
        for (int ks = 0; ks < 2; ks++) {
            const int ckbase = ks * 2;

            uint32_t ahi[2][4], alo[2][4], bh[4][2];
            {
                int ar = (lane & 15);
                int ac = ckbase + (lane >> 4);
#pragma unroll
                for (int fm = 0; fm < 2; fm++) {
                    uint32_t ad = sw_addr(sAhi, wm + fm * 16 + ar, ac);
                    LDSM4(ahi[fm][0], ahi[fm][1], ahi[fm][2], ahi[fm][3], ad);
                    uint32_t ad2 = sw_addr(sAlo, wm + fm * 16 + ar, ac);
                    LDSM4(alo[fm][0], alo[fm][1], alo[fm][2], alo[fm][3], ad2);
                }
                int br = (lane & 7);
                int bsel = (lane >> 4);
                int bc = ckbase + ((lane >> 3) & 1);
#pragma unroll
                for (int fp = 0; fp < 2; fp++) {
                    uint32_t bd = sw_addr(sBh, wn + (fp * 2 + bsel) * 8 + br, bc);
                    uint32_t t0, t1, t2, t3;
                    LDSM4(t0, t1, t2, t3, bd);
                    bh[fp * 2][0] = t0; bh[fp * 2][1] = t1;
                    bh[fp * 2 + 1][0] = t2; bh[fp * 2 + 1][1] = t3;
                }
            }

#pragma unroll
            for (int fm = 0; fm < 2; fm++)
#pragma unroll
                for (int fn = 0; fn < 4; fn++) {
                    MMAH16816(acc[fm][fn], ahi[fm], bh[fn]);
                    MMAH16816(acc[fm][fn], alo[fm], bh[fn]);
                }
        }
    }

    const int lr = lane >> 2;
    const int lc = (lane & 3) * 2;
#pragma unroll
    for (int fm = 0; fm < 2; fm++) {
#pragma unroll
        for (int fn = 0; fn < 4; fn++) {
            int r0 = bm + wm + fm * 16 + lr;
            int cc = bn + wn + fn * 8 + lc;
            if (SPLIT) {
                uint32_t h, l;
                pack_split(acc[fm][fn][0], acc[fm][fn][1], h, l);
                *(uint32_t*)&Chi[(size_t)r0 * N + cc] = h;
                *(uint32_t*)&Clo[(size_t)r0 * N + cc] = l;
                pack_split(acc[fm][fn][2], acc[fm][fn][3], h, l);
                *(uint32_t*)&Chi[(size_t)(r0 + 8) * N + cc] = h;
                *(uint32_t*)&Clo[(size_t)(r0 + 8) * N + cc] = l;
            } else {
                *(float2*)&C[(size_t)r0 * N + cc]       = make_float2(acc[fm][fn][0], acc[fm][fn][1]);
                *(float2*)&C[(size_t)(r0 + 8) * N + cc] = make_float2(acc[fm][fn][2], acc[fm][fn][3]);
            }
        }
    }
}

// ---------------------------------------------------------------------------
// Tensor-core flash attention (bf16 3-pass) — epilogue now emits fp16 pairs.
// Grid (T/128, H, B), 256 threads = 8 warps x 16 q-rows.
// KV tile 64, 3-stage cp.async ring, one __syncthreads per KV tile.
// ---------------------------------------------------------------------------
#define QTILE_B   16384
#define KVSUB_B   8192
#define FSTAGE_B  (4 * KVSUB_B)
#define FSTAGES   3
#define FLASH_SMEM (2 * QTILE_B + FSTAGES * FSTAGE_B)

__global__ __launch_bounds__(256, 1)
void flash_tc_kernel()
{
    extern __shared__ __align__(128) char fsm[];
    const uint32_t sbase = s2u(fsm);
    const uint32_t QHI = sbase;
    const uint32_t QLO = sbase + QTILE_B;
    const uint32_t STG0 = sbase + 2 * QTILE_B;

    const int qt  = blockIdx.x;
    const int h   = blockIdx.y;
    const int b   = blockIdx.z;
    const int kvh = h >> 2;
    const int qb  = qt * 128;

    const int tid = threadIdx.x;
    const int wid = tid >> 5;
    const int lane = tid & 31;

#pragma unroll
    for (int j = 0; j < 4; j++) {
        int i = tid + j * 256;
        int r = i >> 3;
        int ck = i & 7;
        size_t e = (size_t)(b * TT + qb + r) * DD + h * HD + ck * 8;
        CP16(sw128(QHI, r, ck), (const char*)&g_Qhi[e]);
        CP16(sw128(QLO, r, ck), (const char*)&g_Qlo[e]);
    }
    CPCOMMIT();

    auto load_kv = [&](int kt, int s) {
        const uint32_t sb = STG0 + s * FSTAGE_B;
#pragma unroll
        for (int j = 0; j < 2; j++) {
            int i = tid + j * 256;
            int r = i >> 3;
            int ck = i & 7;
            size_t e = (size_t)(b * TT + kt * 64 + r) * DKV + kvh * HD + ck * 8;
            uint32_t so = sw128(sb, r, ck);
            CP16(so,               (const char*)&g_Khi[e]);
            CP16(so + KVSUB_B,     (const char*)&g_Klo[e]);
            CP16(so + 2 * KVSUB_B, (const char*)&g_Vhi[e]);
            CP16(so + 3 * KVSUB_B, (const char*)&g_Vlo[e]);
        }
    };

    const int NT = 2 * (qt + 1);

    load_kv(0, 0); CPCOMMIT();
    if (NT > 1) { load_kv(1, 1); CPCOMMIT(); }

    CPWAIT(2);
    __syncthreads();

    uint32_t qhiF[4][4], qloF[4][4];
    {
        int ar = lane & 15;
        int ac = lane >> 4;
#pragma unroll
        for (int ks = 0; ks < 4; ks++) {
            uint32_t ad = sw128(QHI, wid * 16 + ar, 2 * ks + ac);
            LDSM4(qhiF[ks][0], qhiF[ks][1], qhiF[ks][2], qhiF[ks][3], ad);
            uint32_t ad2 = sw128(QLO, wid * 16 + ar, 2 * ks + ac);
            LDSM4(qloF[ks][0], qloF[ks][1], qloF[ks][2], qloF[ks][3], ad2);
        }
    }

    float oacc[8][4];
#pragma unroll
    for (int i = 0; i < 8; i++)
#pragma unroll
        for (int q = 0; q < 4; q++) oacc[i][q] = 0.f;
    float mrow[2] = {-1e30f, -1e30f};
    float lrow[2] = {0.f, 0.f};

    const int wr = qb + wid * 16;
    const float scale = 0.125f;

    for (int kt = 0; kt < NT; kt++) {
        const int s = kt % FSTAGES;
        const int kb = kt * 64;

        CPWAIT(1);
        __syncthreads();

        if (kt + 2 < NT) {
            load_kv(kt + 2, (kt + 2) % FSTAGES);
            CPCOMMIT();
        }

        const uint32_t KH = STG0 + s * FSTAGE_B;
        const uint32_t KL = KH + KVSUB_B;
        const uint32_t VH = KH + 2 * KVSUB_B;
        const uint32_t VL = KH + 3 * KVSUB_B;

        float sacc[8][4];
#pragma unroll
        for (int i = 0; i < 8; i++)
#pragma unroll
            for (int q = 0; q < 4; q++) sacc[i][q] = 0.f;

        {
            int br = lane & 7;
            int bsel = lane >> 4;
            int bksel = (lane >> 3) & 1;
#pragma unroll
            for (int ks = 0; ks < 4; ks++) {
                int bc = 2 * ks + bksel;
#pragma unroll
                for (int fp = 0; fp < 4; fp++) {
                    int krow = fp * 16 + bsel * 8 + br;
                    uint32_t t0, t1, t2, t3, u0, u1, u2, u3;
                    LDSM4(t0, t1, t2, t3, sw128(KH, krow, bc));
                    LDSM4(u0, u1, u2, u3, sw128(KL, krow, bc));
                    MMA16816R(sacc[2 * fp],     qhiF[ks], t0, t1);
                    MMA16816R(sacc[2 * fp],     qloF[ks], t0, t1);
                    MMA16816R(sacc[2 * fp],     qhiF[ks], u0, u1);
                    MMA16816R(sacc[2 * fp + 1], qhiF[ks], t2, t3);
                    MMA16816R(sacc[2 * fp + 1], qloF[ks], t2, t3);
                    MMA16816R(sacc[2 * fp + 1], qhiF[ks], u2, u3);
                }
            }
        }

        const bool need_mask = (kb + 63 > wr);
#pragma unroll
        for (int fn = 0; fn < 8; fn++)
#pragma unroll
            for (int q = 0; q < 4; q++) sacc[fn][q] *= scale;
        if (need_mask) {
#pragma unroll
            for (int fn = 0; fn < 8; fn++)
#pragma unroll
                for (int q = 0; q < 4; q++) {
                    int kc = kb + fn * 8 + (lane & 3) * 2 + (q & 1);
                    int qr = wr + (lane >> 2) + (q >> 1) * 8;
                    if (kc > qr) sacc[fn][q] = -1e30f;
                }
        }

#pragma unroll
        for (int r = 0; r < 2; r++) {
            float rmax = -1e30f;
#pragma unroll
            for (int fn = 0; fn < 8; fn++) {
                rmax = fmaxf(rmax, sacc[fn][2 * r]);
                rmax = fmaxf(rmax, sacc[fn][2 * r + 1]);
            }
            rmax = fmaxf(rmax, __shfl_xor_sync(0xffffffffu, rmax, 1));
            rmax = fmaxf(rmax, __shfl_xor_sync(0xffffffffu, rmax, 2));

            float mn = fmaxf(mrow[r], rmax);
            float alpha = __expf(mrow[r] - mn);
            mrow[r] = mn;

            float rs = 0.f;
#pragma unroll
            for (int fn = 0; fn < 8; fn++) {
                float p0 = __expf(sacc[fn][2 * r] - mn);
                float p1 = __expf(sacc[fn][2 * r + 1] - mn);
                sacc[fn][2 * r] = p0;
                sacc[fn][2 * r + 1] = p1;
                rs += p0 + p1;
            }
            rs += __shfl_xor_sync(0xffffffffu, rs, 1);
            rs += __shfl_xor_sync(0xffffffffu, rs, 2);
            lrow[r] = lrow[r] * alpha + rs;

#pragma unroll
            for (int fn = 0; fn < 8; fn++) {
                oacc[fn][2 * r]     *= alpha;
                oacc[fn][2 * r + 1] *= alpha;
            }
        }

        {
            int g = lane >> 3;
            int vr_off = (g & 1) * 8 + (lane & 7);
            int vc_off = g >> 1;
#pragma unroll
            for (int ks = 0; ks < 4; ks++) {
                uint32_t phiF[4], ploF[4];
                pack_split(sacc[2 * ks][0],     sacc[2 * ks][1],     phiF[0], ploF[0]);
                pack_split(sacc[2 * ks][2],     sacc[2 * ks][3],     phiF[1], ploF[1]);
                pack_split(sacc[2 * ks + 1][0], sacc[2 * ks + 1][1], phiF[2], ploF[2]);
                pack_split(sacc[2 * ks + 1][2], sacc[2 * ks + 1][3], phiF[3], ploF[3]);

                int vrow = ks * 16 + vr_off;
#pragma unroll
                for (int fv = 0; fv < 4; fv++) {
                    int vchunk = 2 * fv + vc_off;
                    uint32_t t0, t1, t2, t3, u0, u1, u2, u3;
                    LDSM4T(t0, t1, t2, t3, sw128(VH, vrow, vchunk));
                    LDSM4T(u0, u1, u2, u3, sw128(VL, vrow, vchunk));
                    MMA16816R(oacc[2 * fv],     phiF, t0, t1);
                    MMA16816R(oacc[2 * fv],     ploF, t0, t1);
                    MMA16816R(oacc[2 * fv],     phiF, u0, u1);
                    MMA16816R(oacc[2 * fv + 1], phiF, t2, t3);
                    MMA16816R(oacc[2 * fv + 1], ploF, t2, t3);
                    MMA16816R(oacc[2 * fv + 1], phiF, u2, u3);
                }
            }
        }
    }

    // ---- epilogue: normalize, fp16 split, store ----
#pragma unroll
    for (int r = 0; r < 2; r++) {
        float inv = 1.f / lrow[r];
        int row = wr + (lane >> 2) + 8 * r;
#pragma unroll
        for (int fn = 0; fn < 8; fn++) {
            int col = h * HD + fn * 8 + (lane & 3) * 2;
            float x0 = oacc[fn][2 * r] * inv;
            float x1 = oacc[fn][2 * r + 1] * inv;
            uint32_t hv, lv;
            pack_split_h(x0, x1, hv, lv);
            size_t e = (size_t)(b * TT + row) * DD + col;
            *(uint32_t*)&g_Ahi[e] = hv;
            *(uint32_t*)&g_Alo[e] = lv;
        }
    }
}

// ---------------------------------------------------------------------------
// Launch
// ---------------------------------------------------------------------------
extern "C" void kernel_launch(void* const* d_in, const int* in_sizes, int n_in,
                              void* d_out, int out_size)
{
    const float* x  = (const float*)d_in[0];
    const float* Wq = (const float*)d_in[1];
    const float* Wk = (const float*)d_in[2];
    const float* Wv = (const float*)d_in[3];
    const float* Wo = (const float*)d_in[4];
    float* out = (float*)d_out;

    __half *xh, *xl, *wq, *wk, *wv, *wo, *ah, *al;
    __nv_bfloat16 *qh, *ql, *kh, *kl, *vh, *vl;
    cudaGetSymbolAddress((void**)&xh, g_xhi); cudaGetSymbolAddress((void**)&xl, g_xlo);
    cudaGetSymbolAddress((void**)&wq, g_Wq);  cudaGetSymbolAddress((void**)&wk, g_Wk);
    cudaGetSymbolAddress((void**)&wv, g_Wv);  cudaGetSymbolAddress((void**)&wo, g_Wo);
    cudaGetSymbolAddress((void**)&qh, g_Qhi); cudaGetSymbolAddress((void**)&ql, g_Qlo);
    cudaGetSymbolAddress((void**)&kh, g_Khi); cudaGetSymbolAddress((void**)&kl, g_Klo);
    cudaGetSymbolAddress((void**)&vh, g_Vhi); cudaGetSymbolAddress((void**)&vl, g_Vlo);
    cudaGetSymbolAddress((void**)&ah, g_Ahi); cudaGetSymbolAddress((void**)&al, g_Alo);

    cudaFuncSetAttribute(gemm_tc_kernel<true>,
                         cudaFuncAttributeMaxDynamicSharedMemorySize, GEMM_SMEM);
    cudaFuncSetAttribute(gemm_tc_kernel<false>,
                         cudaFuncAttributeMaxDynamicSharedMemorySize, GEMM_SMEM);
    cudaFuncSetAttribute(flash_tc_kernel,
                         cudaFuncAttributeMaxDynamicSharedMemorySize, FLASH_SMEM);

    // fp32 -> fp16 splits/converts
    const int n_x  = MTOT * DD / 4, n_wq = DD * DD / 4, n_wk = DKV * DD / 4;
    split_h_kernel<<<(n_x  + 255) / 256, 256>>>(x,  xh, xl, n_x);
    conv_h_kernel<<<(n_wq + 255) / 256, 256>>>(Wq, wq, n_wq);
    conv_h_kernel<<<(n_wk + 255) / 256, 256>>>(Wk, wk, n_wk);
    conv_h_kernel<<<(n_wk + 255) / 256, 256>>>(Wv, wv, n_wk);
    conv_h_kernel<<<(n_wq + 255) / 256, 256>>>(Wo, wo, n_wq);

    // Projections (fp16 2-pass) -> split bf16 outputs for flash
    gemm_tc_kernel<true><<<dim3(DD / 128, MTOT / 128), 512, GEMM_SMEM>>>(
        xh, xl, wq, nullptr, qh, ql, MTOT, DD, DD);
    gemm_tc_kernel<true><<<dim3(DKV / 128, MTOT / 128), 512, GEMM_SMEM>>>(
        xh, xl, wk, nullptr, kh, kl, MTOT, DKV, DD);
    gemm_tc_kernel<true><<<dim3(DKV / 128, MTOT / 128), 512, GEMM_SMEM>>>(
        xh, xl, wv, nullptr, vh, vl, MTOT, DKV, DD);

    // bf16 3-pass causal GQA flash attention -> fp16 split A
    flash_tc_kernel<<<dim3(TT / 128, HH, BB), 256, FLASH_SMEM>>>();

    // Output projection (fp16 2-pass) -> fp32 out
    gemm_tc_kernel<false><<<dim3(DD / 128, MTOT / 128), 512, GEMM_SMEM>>>(
        ah, al, wo, out, nullptr, nullptr, MTOT, DD, DD);
}

// round 9
// speedup vs baseline: 1.3586x; 1.1098x over previous
#include <cuda_runtime.h>
#include <cuda_bf16.h>
#include <cuda_fp16.h>
#include <cstdint>
#include <math.h>

// Problem constants
#define BB   2
#define TT   2048
#define DD   2048
#define HH   32
#define KVH  8
#define HD   64
#define MTOT (BB*TT)      // 4096
#define DKV  (KVH*HD)     // 512
#define NQKV (DD + 2*DKV) // 3072

// ---------------------------------------------------------------------------
// Scratch (__device__ globals; no allocation allowed)
// ---------------------------------------------------------------------------
__device__ __half g_xhi[(size_t)MTOT * DD], g_xlo[(size_t)MTOT * DD];
__device__ __half g_Wqkv[(size_t)NQKV * DD];           // [Wq; Wk; Wv] fp16
__device__ __half g_Wo[(size_t)DD * DD];

__device__ __half g_Qhi[(size_t)MTOT * DD], g_Qlo[(size_t)MTOT * DD];
__device__ __half g_K[(size_t)MTOT * DKV];
__device__ __half g_V[(size_t)MTOT * DKV];
__device__ __half g_Ahi[(size_t)MTOT * DD], g_Alo[(size_t)MTOT * DD];

// ---------------------------------------------------------------------------
// Helpers (portable PTX only: cp.async / ldmatrix / mma.sync)
// ---------------------------------------------------------------------------
__device__ __forceinline__ uint32_t s2u(const void* p) {
    return (uint32_t)__cvta_generic_to_shared(p);
}

#define CP16(sa, ga) \
    asm volatile("cp.async.cg.shared.global [%0], [%1], 16;" :: "r"(sa), "l"(ga) : "memory")
#define CPCOMMIT()  asm volatile("cp.async.commit_group;" ::: "memory")
#define CPWAIT(n)   asm volatile("cp.async.wait_group %0;" :: "n"(n) : "memory")

#define LDSM4(r0, r1, r2, r3, addr) \
    asm volatile("ldmatrix.sync.aligned.m8n8.x4.shared.b16 {%0,%1,%2,%3}, [%4];" \
        : "=r"(r0), "=r"(r1), "=r"(r2), "=r"(r3) : "r"(addr))

#define LDSM4T(r0, r1, r2, r3, addr) \
    asm volatile("ldmatrix.sync.aligned.m8n8.x4.trans.shared.b16 {%0,%1,%2,%3}, [%4];" \
        : "=r"(r0), "=r"(r1), "=r"(r2), "=r"(r3) : "r"(addr))

// fp16 mma, b from array
#define MMAH16816(d, a, b) \
    asm volatile("mma.sync.aligned.m16n8k16.row.col.f32.f16.f16.f32 " \
        "{%0,%1,%2,%3}, {%4,%5,%6,%7}, {%8,%9}, {%0,%1,%2,%3};" \
        : "+f"((d)[0]), "+f"((d)[1]), "+f"((d)[2]), "+f"((d)[3]) \
        : "r"((a)[0]), "r"((a)[1]), "r"((a)[2]), "r"((a)[3]), "r"((b)[0]), "r"((b)[1]))

// fp16 mma, b from scalars
#define MMAH16816R(d, a, b0v, b1v) \
    asm volatile("mma.sync.aligned.m16n8k16.row.col.f32.f16.f16.f32 " \
        "{%0,%1,%2,%3}, {%4,%5,%6,%7}, {%8,%9}, {%0,%1,%2,%3};" \
        : "+f"((d)[0]), "+f"((d)[1]), "+f"((d)[2]), "+f"((d)[3]) \
        : "r"((a)[0]), "r"((a)[1]), "r"((a)[2]), "r"((a)[3]), "r"(b0v), "r"(b1v))

// 64B-row swizzle (GEMM tiles)
__device__ __forceinline__ uint32_t sw_addr(uint32_t base, int row, int chunk) {
    return base + row * 64 + ((chunk ^ ((row >> 1) & 3)) << 4);
}
// 128B-row swizzle (flash tiles)
__device__ __forceinline__ uint32_t sw128(uint32_t base, int row, int chunk) {
    return base + row * 128 + ((chunk ^ (row & 7)) << 4);
}

// fp32 pair -> packed fp16x2 hi/lo
__device__ __forceinline__ void pack_split_h(float x0, float x1, uint32_t& hi, uint32_t& lo) {
    __half h0 = __float2half_rn(x0);
    __half h1 = __float2half_rn(x1);
    __half l0 = __float2half_rn(x0 - __half2float(h0));
    __half l1 = __float2half_rn(x1 - __half2float(h1));
    __half2 hp = __halves2half2(h0, h1), lp = __halves2half2(l0, l1);
    hi = *(uint32_t*)&hp;
    lo = *(uint32_t*)&lp;
}

__device__ __forceinline__ uint32_t pack_h2(float x0, float x1) {
    __half2 p = __halves2half2(__float2half_rn(x0), __float2half_rn(x1));
    return *(uint32_t*)&p;
}

// ---------------------------------------------------------------------------
// fp32 -> fp16 hi/lo split kernel
// ---------------------------------------------------------------------------
__global__ __launch_bounds__(256)
void split_h_kernel(const float* __restrict__ src, __half* __restrict__ hi,
                    __half* __restrict__ lo, int n4)
{
    int i = blockIdx.x * blockDim.x + threadIdx.x;
    if (i >= n4) return;
    float4 v = ((const float4*)src)[i];
    uint32_t h0, l0, h1, l1;
    pack_split_h(v.x, v.y, h0, l0);
    pack_split_h(v.z, v.w, h1, l1);
    ((uint2*)hi)[i] = make_uint2(h0, h1);
    ((uint2*)lo)[i] = make_uint2(l0, l1);
}

// fp32 -> fp16 convert kernel
__global__ __launch_bounds__(256)
void conv_h_kernel(const float* __restrict__ src, __half* __restrict__ dst, int n4)
{
    int i = blockIdx.x * blockDim.x + threadIdx.x;
    if (i >= n4) return;
    float4 v = ((const float4*)src)[i];
    ((uint2*)dst)[i] = make_uint2(pack_h2(v.x, v.y), pack_h2(v.z, v.w));
}

// ---------------------------------------------------------------------------
// fp16 2-pass GEMM:  C = (Ahi+Alo) * Bh^T
// CTA 128x128, BK=32, 4-stage cp.async, one __syncthreads per chunk.
// 512 threads = 16 warps (4x4), warp tile 32x32.
// MODE 0: QKV epilogue (Q -> fp16 hi/lo pair, K/V -> single fp16)
// MODE 1: fp32 C
// ---------------------------------------------------------------------------
#define STAGES      4
#define TILE_B      8192
#define STAGE_B     (3 * TILE_B)            // 24 KB
#define GEMM_SMEM   (STAGES * STAGE_B)      // 96 KB

template<int MODE>
__global__ __launch_bounds__(512)
void gemm_tc_kernel(const __half* __restrict__ Ahi, const __half* __restrict__ Alo,
                    const __half* __restrict__ Bh,
                    float* __restrict__ C,
                    __half* __restrict__ Qhi, __half* __restrict__ Qlo,
                    __half* __restrict__ Kh, __half* __restrict__ Vh,
                    int M, int N, int K)
{
    extern __shared__ __align__(128) char smem[];
    const uint32_t sbase = s2u(smem);

    const int tid = threadIdx.x;
    const int wid = tid >> 5;
    const int lane = tid & 31;
    const int bm = blockIdx.y * 128;
    const int bn = blockIdx.x * 128;

    const int wm = (wid & 3) * 32;
    const int wn = (wid >> 2) * 32;

    const char* srcs[3] = {(const char*)Ahi, (const char*)Alo, (const char*)Bh};
    const size_t rowstride = (size_t)K * 2;

    const int NC = K >> 5;

    auto load_chunk = [&](int c, int s) {
        const uint32_t sb = sbase + s * STAGE_B;
        const size_t k0b = (size_t)c * 64;
#pragma unroll
        for (int t = 0; t < 3; t++) {
            const int rbase = (t < 2) ? bm : bn;
            const char* src = srcs[t];
            int r = tid >> 2;
            int ck = tid & 3;
            const char* ga = src + (size_t)(rbase + r) * rowstride + k0b + ck * 16;
            CP16(sw_addr(sb + t * TILE_B, r, ck), ga);
        }
    };

    float acc[2][4][4];
#pragma unroll
    for (int i = 0; i < 2; i++)
#pragma unroll
        for (int j = 0; j < 4; j++)
#pragma unroll
            for (int q = 0; q < 4; q++) acc[i][j][q] = 0.f;

    load_chunk(0, 0); CPCOMMIT();
    load_chunk(1, 1); CPCOMMIT();
    load_chunk(2, 2); CPCOMMIT();

    for (int c = 0; c < NC; c++) {
        const int s = c & 3;
        CPWAIT(2);
        __syncthreads();

        if (c + 3 < NC) {
            load_chunk(c + 3, (c + 3) & 3);
            CPCOMMIT();
        }

        const uint32_t sb   = sbase + s * STAGE_B;
        const uint32_t sAhi = sb;
        const uint32_t sAlo = sb + TILE_B;
        const uint32_t sBh  = sb + 2 * TILE_B;

#pragma unroll
        for (int ks = 0; ks < 2; ks++) {
            const int ckbase = ks * 2;

            uint32_t ahi[2][4], alo[2][4], bh[4][2];
            {
                int ar = (lane & 15);
                int ac = ckbase + (lane >> 4);
#pragma unroll
                for (int fm = 0; fm < 2; fm++) {
                    uint32_t ad = sw_addr(sAhi, wm + fm * 16 + ar, ac);
                    LDSM4(ahi[fm][0], ahi[fm][1], ahi[fm][2], ahi[fm][3], ad);
                    uint32_t ad2 = sw_addr(sAlo, wm + fm * 16 + ar, ac);
                    LDSM4(alo[fm][0], alo[fm][1], alo[fm][2], alo[fm][3], ad2);
                }
                int br = (lane & 7);
                int bsel = (lane >> 4);
                int bc = ckbase + ((lane >> 3) & 1);
#pragma unroll
                for (int fp = 0; fp < 2; fp++) {
                    uint32_t bd = sw_addr(sBh, wn + (fp * 2 + bsel) * 8 + br, bc);
                    uint32_t t0, t1, t2, t3;
                    LDSM4(t0, t1, t2, t3, bd);
                    bh[fp * 2][0] = t0; bh[fp * 2][1] = t1;
                    bh[fp * 2 + 1][0] = t2; bh[fp * 2 + 1][1] = t3;
                }
            }

#pragma unroll
            for (int fm = 0; fm < 2; fm++)
#pragma unroll
                for (int fn = 0; fn < 4; fn++) {
                    MMAH16816(acc[fm][fn], ahi[fm], bh[fn]);
                    MMAH16816(acc[fm][fn], alo[fm], bh[fn]);
                }
        }
    }

    const int lr = lane >> 2;
    const int lc = (lane & 3) * 2;
#pragma unroll
    for (int fm = 0; fm < 2; fm++) {
#pragma unroll
        for (int fn = 0; fn < 4; fn++) {
            int r0 = bm + wm + fm * 16 + lr;
            int cc = bn + wn + fn * 8 + lc;
            if (MODE == 0) {
                if (bn < DD) {                   // Q segment -> split pair
                    uint32_t h, l;
                    pack_split_h(acc[fm][fn][0], acc[fm][fn][1], h, l);
                    *(uint32_t*)&Qhi[(size_t)r0 * DD + cc] = h;
                    *(uint32_t*)&Qlo[(size_t)r0 * DD + cc] = l;
                    pack_split_h(acc[fm][fn][2], acc[fm][fn][3], h, l);
                    *(uint32_t*)&Qhi[(size_t)(r0 + 8) * DD + cc] = h;
                    *(uint32_t*)&Qlo[(size_t)(r0 + 8) * DD + cc] = l;
                } else if (bn < DD + DKV) {      // K segment -> single fp16
                    int kc = cc - DD;
                    *(uint32_t*)&Kh[(size_t)r0 * DKV + kc] =
                        pack_h2(acc[fm][fn][0], acc[fm][fn][1]);
                    *(uint32_t*)&Kh[(size_t)(r0 + 8) * DKV + kc] =
                        pack_h2(acc[fm][fn][2], acc[fm][fn][3]);
                } else {                         // V segment -> single fp16
                    int vc = cc - DD - DKV;
                    *(uint32_t*)&Vh[(size_t)r0 * DKV + vc] =
                        pack_h2(acc[fm][fn][0], acc[fm][fn][1]);
                    *(uint32_t*)&Vh[(size_t)(r0 + 8) * DKV + vc] =
                        pack_h2(acc[fm][fn][2], acc[fm][fn][3]);
                }
            } else {
                *(float2*)&C[(size_t)r0 * N + cc]       = make_float2(acc[fm][fn][0], acc[fm][fn][1]);
                *(float2*)&C[(size_t)(r0 + 8) * N + cc] = make_float2(acc[fm][fn][2], acc[fm][fn][3]);
            }
        }
    }
}

// ---------------------------------------------------------------------------
// Tensor-core flash attention (fp16 2-pass).
// Grid (T/128, H, B), 256 threads = 8 warps x 16 q-rows.
// KV tile 64 (K+V single fp16, 16KB/stage), 3-stage cp.async ring.
// SMEM: Qhi+Qlo 32KB + 3 x 16KB = 80KB.
// ---------------------------------------------------------------------------
#define QTILE_B   16384
#define KVSUB_B   8192
#define FSTAGE_B  (2 * KVSUB_B)
#define FSTAGES   3
#define FLASH_SMEM (2 * QTILE_B + FSTAGES * FSTAGE_B)

__global__ __launch_bounds__(256, 1)
void flash_tc_kernel()
{
    extern __shared__ __align__(128) char fsm[];
    const uint32_t sbase = s2u(fsm);
    const uint32_t QHI = sbase;
    const uint32_t QLO = sbase + QTILE_B;
    const uint32_t STG0 = sbase + 2 * QTILE_B;

    const int qt  = blockIdx.x;
    const int h   = blockIdx.y;
    const int b   = blockIdx.z;
    const int kvh = h >> 2;
    const int qb  = qt * 128;

    const int tid = threadIdx.x;
    const int wid = tid >> 5;
    const int lane = tid & 31;

    // ---- load Q tile (hi/lo fp16) ----
#pragma unroll
    for (int j = 0; j < 4; j++) {
        int i = tid + j * 256;
        int r = i >> 3;
        int ck = i & 7;
        size_t e = (size_t)(b * TT + qb + r) * DD + h * HD + ck * 8;
        CP16(sw128(QHI, r, ck), (const char*)&g_Qhi[e]);
        CP16(sw128(QLO, r, ck), (const char*)&g_Qlo[e]);
    }
    CPCOMMIT();

    auto load_kv = [&](int kt, int s) {
        const uint32_t sb = STG0 + s * FSTAGE_B;
#pragma unroll
        for (int j = 0; j < 2; j++) {
            int i = tid + j * 256;
            int r = i >> 3;
            int ck = i & 7;
            size_t e = (size_t)(b * TT + kt * 64 + r) * DKV + kvh * HD + ck * 8;
            uint32_t so = sw128(sb, r, ck);
            CP16(so,           (const char*)&g_K[e]);
            CP16(so + KVSUB_B, (const char*)&g_V[e]);
        }
    };

    const int NT = 2 * (qt + 1);

    load_kv(0, 0); CPCOMMIT();
    if (NT > 1) { load_kv(1, 1); CPCOMMIT(); }

    CPWAIT(2);
    __syncthreads();

    // ---- Q fragments (register-resident) ----
    uint32_t qhiF[4][4], qloF[4][4];
    {
        int ar = lane & 15;
        int ac = lane >> 4;
#pragma unroll
        for (int ks = 0; ks < 4; ks++) {
            uint32_t ad = sw128(QHI, wid * 16 + ar, 2 * ks + ac);
            LDSM4(qhiF[ks][0], qhiF[ks][1], qhiF[ks][2], qhiF[ks][3], ad);
            uint32_t ad2 = sw128(QLO, wid * 16 + ar, 2 * ks + ac);
            LDSM4(qloF[ks][0], qloF[ks][1], qloF[ks][2], qloF[ks][3], ad2);
        }
    }

    float oacc[8][4];
#pragma unroll
    for (int i = 0; i < 8; i++)
#pragma unroll
        for (int q = 0; q < 4; q++) oacc[i][q] = 0.f;
    float mrow[2] = {-1e30f, -1e30f};
    float lrow[2] = {0.f, 0.f};

    const int wr = qb + wid * 16;
    const float scale = 0.125f;

    for (int kt = 0; kt < NT; kt++) {
        const int s = kt % FSTAGES;
        const int kb = kt * 64;

        CPWAIT(1);
        __syncthreads();

        if (kt + 2 < NT) {
            load_kv(kt + 2, (kt + 2) % FSTAGES);
            CPCOMMIT();
        }

        const uint32_t KH = STG0 + s * FSTAGE_B;
        const uint32_t VH = KH + KVSUB_B;

        // ---- S = Q K^T (2-pass fp16) ----
        float sacc[8][4];
#pragma unroll
        for (int i = 0; i < 8; i++)
#pragma unroll
            for (int q = 0; q < 4; q++) sacc[i][q] = 0.f;

        {
            int br = lane & 7;
            int bsel = lane >> 4;
            int bksel = (lane >> 3) & 1;
#pragma unroll
            for (int ks = 0; ks < 4; ks++) {
                int bc = 2 * ks + bksel;
#pragma unroll
                for (int fp = 0; fp < 4; fp++) {
                    int krow = fp * 16 + bsel * 8 + br;
                    uint32_t t0, t1, t2, t3;
                    LDSM4(t0, t1, t2, t3, sw128(KH, krow, bc));
                    MMAH16816R(sacc[2 * fp],     qhiF[ks], t0, t1);
                    MMAH16816R(sacc[2 * fp],     qloF[ks], t0, t1);
                    MMAH16816R(sacc[2 * fp + 1], qhiF[ks], t2, t3);
                    MMAH16816R(sacc[2 * fp + 1], qloF[ks], t2, t3);
                }
            }
        }

        // ---- scale + causal mask ----
        const bool need_mask = (kb + 63 > wr);
#pragma unroll
        for (int fn = 0; fn < 8; fn++)
#pragma unroll
            for (int q = 0; q < 4; q++) sacc[fn][q] *= scale;
        if (need_mask) {
#pragma unroll
            for (int fn = 0; fn < 8; fn++)
#pragma unroll
                for (int q = 0; q < 4; q++) {
                    int kc = kb + fn * 8 + (lane & 3) * 2 + (q & 1);
                    int qr = wr + (lane >> 2) + (q >> 1) * 8;
                    if (kc > qr) sacc[fn][q] = -1e30f;
                }
        }

        // ---- online softmax ----
#pragma unroll
        for (int r = 0; r < 2; r++) {
            float rmax = -1e30f;
#pragma unroll
            for (int fn = 0; fn < 8; fn++) {
                rmax = fmaxf(rmax, sacc[fn][2 * r]);
                rmax = fmaxf(rmax, sacc[fn][2 * r + 1]);
            }
            rmax = fmaxf(rmax, __shfl_xor_sync(0xffffffffu, rmax, 1));
            rmax = fmaxf(rmax, __shfl_xor_sync(0xffffffffu, rmax, 2));

            float mn = fmaxf(mrow[r], rmax);
            float alpha = __expf(mrow[r] - mn);
            mrow[r] = mn;

            float rs = 0.f;
#pragma unroll
            for (int fn = 0; fn < 8; fn++) {
                float p0 = __expf(sacc[fn][2 * r] - mn);
                float p1 = __expf(sacc[fn][2 * r + 1] - mn);
                sacc[fn][2 * r] = p0;
                sacc[fn][2 * r + 1] = p1;
                rs += p0 + p1;
            }
            rs += __shfl_xor_sync(0xffffffffu, rs, 1);
            rs += __shfl_xor_sync(0xffffffffu, rs, 2);
            lrow[r] = lrow[r] * alpha + rs;

#pragma unroll
            for (int fn = 0; fn < 8; fn++) {
                oacc[fn][2 * r]     *= alpha;
                oacc[fn][2 * r + 1] *= alpha;
            }
        }

        // ---- O += P V (P split fp16 2-pass, V single) ----
        {
            int g = lane >> 3;
            int vr_off = (g & 1) * 8 + (lane & 7);
            int vc_off = g >> 1;
#pragma unroll
            for (int ks = 0; ks < 4; ks++) {
                uint32_t phiF[4], ploF[4];
                pack_split_h(sacc[2 * ks][0],     sacc[2 * ks][1],     phiF[0], ploF[0]);
                pack_split_h(sacc[2 * ks][2],     sacc[2 * ks][3],     phiF[1], ploF[1]);
                pack_split_h(sacc[2 * ks + 1][0], sacc[2 * ks + 1][1], phiF[2], ploF[2]);
                pack_split_h(sacc[2 * ks + 1][2], sacc[2 * ks + 1][3], phiF[3], ploF[3]);

                int vrow = ks * 16 + vr_off;
#pragma unroll
                for (int fv = 0; fv < 4; fv++) {
                    int vchunk = 2 * fv + vc_off;
                    uint32_t t0, t1, t2, t3;
                    LDSM4T(t0, t1, t2, t3, sw128(VH, vrow, vchunk));
                    MMAH16816R(oacc[2 * fv],     phiF, t0, t1);
                    MMAH16816R(oacc[2 * fv],     ploF, t0, t1);
                    MMAH16816R(oacc[2 * fv + 1], phiF, t2, t3);
                    MMAH16816R(oacc[2 * fv + 1], ploF, t2, t3);
                }
            }
        }
    }

    // ---- epilogue: normalize, fp16 split, store ----
#pragma unroll
    for (int r = 0; r < 2; r++) {
        float inv = 1.f / lrow[r];
        int row = wr + (lane >> 2) + 8 * r;
#pragma unroll
        for (int fn = 0; fn < 8; fn++) {
            int col = h * HD + fn * 8 + (lane & 3) * 2;
            float x0 = oacc[fn][2 * r] * inv;
            float x1 = oacc[fn][2 * r + 1] * inv;
            uint32_t hv, lv;
            pack_split_h(x0, x1, hv, lv);
            size_t e = (size_t)(b * TT + row) * DD + col;
            *(uint32_t*)&g_Ahi[e] = hv;
            *(uint32_t*)&g_Alo[e] = lv;
        }
    }
}

// ---------------------------------------------------------------------------
// Launch
// ---------------------------------------------------------------------------
extern "C" void kernel_launch(void* const* d_in, const int* in_sizes, int n_in,
                              void* d_out, int out_size)
{
    const float* x  = (const float*)d_in[0];
    const float* Wq = (const float*)d_in[1];
    const float* Wk = (const float*)d_in[2];
    const float* Wv = (const float*)d_in[3];
    const float* Wo = (const float*)d_in[4];
    float* out = (float*)d_out;

    __half *xh, *xl, *wqkv, *wo, *qh, *ql, *kh, *vh, *ah, *al;
    cudaGetSymbolAddress((void**)&xh, g_xhi);  cudaGetSymbolAddress((void**)&xl, g_xlo);
    cudaGetSymbolAddress((void**)&wqkv, g_Wqkv);
    cudaGetSymbolAddress((void**)&wo, g_Wo);
    cudaGetSymbolAddress((void**)&qh, g_Qhi);  cudaGetSymbolAddress((void**)&ql, g_Qlo);
    cudaGetSymbolAddress((void**)&kh, g_K);    cudaGetSymbolAddress((void**)&vh, g_V);
    cudaGetSymbolAddress((void**)&ah, g_Ahi);  cudaGetSymbolAddress((void**)&al, g_Alo);

    cudaFuncSetAttribute(gemm_tc_kernel<0>,
                         cudaFuncAttributeMaxDynamicSharedMemorySize, GEMM_SMEM);
    cudaFuncSetAttribute(gemm_tc_kernel<1>,
                         cudaFuncAttributeMaxDynamicSharedMemorySize, GEMM_SMEM);
    cudaFuncSetAttribute(flash_tc_kernel,
                         cudaFuncAttributeMaxDynamicSharedMemorySize, FLASH_SMEM);

    // fp32 -> fp16 splits/converts (Wq/Wk/Wv concatenated into g_Wqkv)
    const int n_x  = MTOT * DD / 4, n_wq = DD * DD / 4, n_wk = DKV * DD / 4;
    split_h_kernel<<<(n_x  + 255) / 256, 256>>>(x,  xh, xl, n_x);
    conv_h_kernel<<<(n_wq + 255) / 256, 256>>>(Wq, wqkv, n_wq);
    conv_h_kernel<<<(n_wk + 255) / 256, 256>>>(Wk, wqkv + (size_t)DD * DD, n_wk);
    conv_h_kernel<<<(n_wk + 255) / 256, 256>>>(Wv, wqkv + (size_t)(DD + DKV) * DD, n_wk);
    conv_h_kernel<<<(n_wq + 255) / 256, 256>>>(Wo, wo, n_wq);

    // Merged QKV projection (fp16 2-pass)
    gemm_tc_kernel<0><<<dim3(NQKV / 128, MTOT / 128), 512, GEMM_SMEM>>>(
        xh, xl, wqkv, nullptr, qh, ql, kh, vh, MTOT, NQKV, DD);

    // fp16 2-pass causal GQA flash attention -> fp16 split A
    flash_tc_kernel<<<dim3(TT / 128, HH, BB), 256, FLASH_SMEM>>>();

    // Output projection (fp16 2-pass) -> fp32 out
    gemm_tc_kernel<1><<<dim3(DD / 128, MTOT / 128), 512, GEMM_SMEM>>>(
        ah, al, wo, out, nullptr, nullptr, nullptr, nullptr, MTOT, DD, DD);
}

// round 10
// speedup vs baseline: 2.1677x; 1.5955x over previous
#include <cuda_runtime.h>
#include <cuda_fp16.h>
#include <cstdint>
#include <math.h>

// Problem constants
#define BB   2
#define TT   2048
#define DD   2048
#define HH   32
#define KVH  8
#define HD   64
#define MTOT (BB*TT)      // 4096
#define DKV  (KVH*HD)     // 512
#define NQKV (DD + 2*DKV) // 3072

// ---------------------------------------------------------------------------
// Scratch (__device__ globals; no allocation allowed) — all single fp16
// ---------------------------------------------------------------------------
__device__ __half g_x[(size_t)MTOT * DD];
__device__ __half g_Wqkv[(size_t)NQKV * DD];           // [Wq; Wk; Wv]
__device__ __half g_Wo[(size_t)DD * DD];

__device__ __half g_Q[(size_t)MTOT * DD];
__device__ __half g_K[(size_t)MTOT * DKV];
__device__ __half g_V[(size_t)MTOT * DKV];
__device__ __half g_A[(size_t)MTOT * DD];

// ---------------------------------------------------------------------------
// Helpers (portable PTX only: cp.async / ldmatrix / mma.sync)
// ---------------------------------------------------------------------------
__device__ __forceinline__ uint32_t s2u(const void* p) {
    return (uint32_t)__cvta_generic_to_shared(p);
}

#define CP16(sa, ga) \
    asm volatile("cp.async.cg.shared.global [%0], [%1], 16;" :: "r"(sa), "l"(ga) : "memory")
#define CPCOMMIT()  asm volatile("cp.async.commit_group;" ::: "memory")
#define CPWAIT(n)   asm volatile("cp.async.wait_group %0;" :: "n"(n) : "memory")

#define LDSM4(r0, r1, r2, r3, addr) \
    asm volatile("ldmatrix.sync.aligned.m8n8.x4.shared.b16 {%0,%1,%2,%3}, [%4];" \
        : "=r"(r0), "=r"(r1), "=r"(r2), "=r"(r3) : "r"(addr))

#define LDSM4T(r0, r1, r2, r3, addr) \
    asm volatile("ldmatrix.sync.aligned.m8n8.x4.trans.shared.b16 {%0,%1,%2,%3}, [%4];" \
        : "=r"(r0), "=r"(r1), "=r"(r2), "=r"(r3) : "r"(addr))

// fp16 mma, b from array
#define MMAH16816(d, a, b) \
    asm volatile("mma.sync.aligned.m16n8k16.row.col.f32.f16.f16.f32 " \
        "{%0,%1,%2,%3}, {%4,%5,%6,%7}, {%8,%9}, {%0,%1,%2,%3};" \
        : "+f"((d)[0]), "+f"((d)[1]), "+f"((d)[2]), "+f"((d)[3]) \
        : "r"((a)[0]), "r"((a)[1]), "r"((a)[2]), "r"((a)[3]), "r"((b)[0]), "r"((b)[1]))

// fp16 mma, b from scalars
#define MMAH16816R(d, a, b0v, b1v) \
    asm volatile("mma.sync.aligned.m16n8k16.row.col.f32.f16.f16.f32 " \
        "{%0,%1,%2,%3}, {%4,%5,%6,%7}, {%8,%9}, {%0,%1,%2,%3};" \
        : "+f"((d)[0]), "+f"((d)[1]), "+f"((d)[2]), "+f"((d)[3]) \
        : "r"((a)[0]), "r"((a)[1]), "r"((a)[2]), "r"((a)[3]), "r"(b0v), "r"(b1v))

// 64B-row swizzle (GEMM tiles)
__device__ __forceinline__ uint32_t sw_addr(uint32_t base, int row, int chunk) {
    return base + row * 64 + ((chunk ^ ((row >> 1) & 3)) << 4);
}
// 128B-row swizzle (flash tiles)
__device__ __forceinline__ uint32_t sw128(uint32_t base, int row, int chunk) {
    return base + row * 128 + ((chunk ^ (row & 7)) << 4);
}

__device__ __forceinline__ uint32_t pack_h2(float x0, float x1) {
    __half2 p = __halves2half2(__float2half_rn(x0), __float2half_rn(x1));
    return *(uint32_t*)&p;
}

// ---------------------------------------------------------------------------
// fp32 -> fp16 convert kernel
// ---------------------------------------------------------------------------
__global__ __launch_bounds__(256)
void conv_h_kernel(const float* __restrict__ src, __half* __restrict__ dst, int n4)
{
    int i = blockIdx.x * blockDim.x + threadIdx.x;
    if (i >= n4) return;
    float4 v = ((const float4*)src)[i];
    ((uint2*)dst)[i] = make_uint2(pack_h2(v.x, v.y), pack_h2(v.z, v.w));
}

// ---------------------------------------------------------------------------
// fp16 1-pass GEMM:  C = A * B^T
// CTA 128x128, BK=32, 4-stage cp.async, one __syncthreads per chunk.
// 512 threads = 16 warps (4x4), warp tile 32x32.
// MODE 0: QKV epilogue (Q/K/V fp16 to separate buffers)
// MODE 1: fp32 C
// ---------------------------------------------------------------------------
#define STAGES      4
#define TILE_B      8192
#define STAGE_B     (2 * TILE_B)            // 16 KB
#define GEMM_SMEM   (STAGES * STAGE_B)      // 64 KB

template<int MODE>
__global__ __launch_bounds__(512)
void gemm_tc_kernel(const __half* __restrict__ Ah, const __half* __restrict__ Bh,
                    float* __restrict__ C,
                    __half* __restrict__ Qo, __half* __restrict__ Ko, __half* __restrict__ Vo,
                    int M, int N, int K)
{
    extern __shared__ __align__(128) char smem[];
    const uint32_t sbase = s2u(smem);

    const int tid = threadIdx.x;
    const int wid = tid >> 5;
    const int lane = tid & 31;
    const int bm = blockIdx.y * 128;
    const int bn = blockIdx.x * 128;

    const int wm = (wid & 3) * 32;
    const int wn = (wid >> 2) * 32;

    const size_t rowstride = (size_t)K * 2;
    const int NC = K >> 5;

    auto load_chunk = [&](int c, int s) {
        const uint32_t sb = sbase + s * STAGE_B;
        const size_t k0b = (size_t)c * 64;
        int r = tid >> 2;
        int ck = tid & 3;
        const char* gaA = (const char*)Ah + (size_t)(bm + r) * rowstride + k0b + ck * 16;
        CP16(sw_addr(sb, r, ck), gaA);
        const char* gaB = (const char*)Bh + (size_t)(bn + r) * rowstride + k0b + ck * 16;
        CP16(sw_addr(sb + TILE_B, r, ck), gaB);
    };

    float acc[2][4][4];
#pragma unroll
    for (int i = 0; i < 2; i++)
#pragma unroll
        for (int j = 0; j < 4; j++)
#pragma unroll
            for (int q = 0; q < 4; q++) acc[i][j][q] = 0.f;

    load_chunk(0, 0); CPCOMMIT();
    load_chunk(1, 1); CPCOMMIT();
    load_chunk(2, 2); CPCOMMIT();

    for (int c = 0; c < NC; c++) {
        const int s = c & 3;
        CPWAIT(2);
        __syncthreads();

        if (c + 3 < NC) {
            load_chunk(c + 3, (c + 3) & 3);
            CPCOMMIT();
        }

        const uint32_t sA = sbase + s * STAGE_B;
        const uint32_t sB = sA + TILE_B;

#pragma unroll
        for (int ks = 0; ks < 2; ks++) {
            const int ckbase = ks * 2;

            uint32_t af[2][4], bf[4][2];
            {
                int ar = (lane & 15);
                int ac = ckbase + (lane >> 4);
#pragma unroll
                for (int fm = 0; fm < 2; fm++) {
                    uint32_t ad = sw_addr(sA, wm + fm * 16 + ar, ac);
                    LDSM4(af[fm][0], af[fm][1], af[fm][2], af[fm][3], ad);
                }
                int br = (lane & 7);
                int bsel = (lane >> 4);
                int bc = ckbase + ((lane >> 3) & 1);
#pragma unroll
                for (int fp = 0; fp < 2; fp++) {
                    uint32_t bd = sw_addr(sB, wn + (fp * 2 + bsel) * 8 + br, bc);
                    uint32_t t0, t1, t2, t3;
                    LDSM4(t0, t1, t2, t3, bd);
                    bf[fp * 2][0] = t0; bf[fp * 2][1] = t1;
                    bf[fp * 2 + 1][0] = t2; bf[fp * 2 + 1][1] = t3;
                }
            }

#pragma unroll
            for (int fm = 0; fm < 2; fm++)
#pragma unroll
                for (int fn = 0; fn < 4; fn++)
                    MMAH16816(acc[fm][fn], af[fm], bf[fn]);
        }
    }

    const int lr = lane >> 2;
    const int lc = (lane & 3) * 2;
#pragma unroll
    for (int fm = 0; fm < 2; fm++) {
#pragma unroll
        for (int fn = 0; fn < 4; fn++) {
            int r0 = bm + wm + fm * 16 + lr;
            int cc = bn + wn + fn * 8 + lc;
            if (MODE == 0) {
                if (bn < DD) {
                    *(uint32_t*)&Qo[(size_t)r0 * DD + cc] =
                        pack_h2(acc[fm][fn][0], acc[fm][fn][1]);
                    *(uint32_t*)&Qo[(size_t)(r0 + 8) * DD + cc] =
                        pack_h2(acc[fm][fn][2], acc[fm][fn][3]);
                } else if (bn < DD + DKV) {
                    int kc = cc - DD;
                    *(uint32_t*)&Ko[(size_t)r0 * DKV + kc] =
                        pack_h2(acc[fm][fn][0], acc[fm][fn][1]);
                    *(uint32_t*)&Ko[(size_t)(r0 + 8) * DKV + kc] =
                        pack_h2(acc[fm][fn][2], acc[fm][fn][3]);
                } else {
                    int vc = cc - DD - DKV;
                    *(uint32_t*)&Vo[(size_t)r0 * DKV + vc] =
                        pack_h2(acc[fm][fn][0], acc[fm][fn][1]);
                    *(uint32_t*)&Vo[(size_t)(r0 + 8) * DKV + vc] =
                        pack_h2(acc[fm][fn][2], acc[fm][fn][3]);
                }
            } else {
                *(float2*)&C[(size_t)r0 * N + cc]       = make_float2(acc[fm][fn][0], acc[fm][fn][1]);
                *(float2*)&C[(size_t)(r0 + 8) * N + cc] = make_float2(acc[fm][fn][2], acc[fm][fn][3]);
            }
        }
    }
}

// ---------------------------------------------------------------------------
// Tensor-core flash attention (fp16 1-pass).
// Grid (T/128, H, B), 256 threads = 8 warps x 16 q-rows.
// KV tile 64 (K+V fp16, 16KB/stage), 3-stage cp.async ring.
// SMEM: Q 16KB + 3 x 16KB = 64KB.
// ---------------------------------------------------------------------------
#define QTILE_B   16384
#define KVSUB_B   8192
#define FSTAGE_B  (2 * KVSUB_B)
#define FSTAGES   3
#define FLASH_SMEM (QTILE_B + FSTAGES * FSTAGE_B)

__global__ __launch_bounds__(256, 1)
void flash_tc_kernel()
{
    extern __shared__ __align__(128) char fsm[];
    const uint32_t sbase = s2u(fsm);
    const uint32_t QT = sbase;
    const uint32_t STG0 = sbase + QTILE_B;

    const int qt  = blockIdx.x;
    const int h   = blockIdx.y;
    const int b   = blockIdx.z;
    const int kvh = h >> 2;
    const int qb  = qt * 128;

    const int tid = threadIdx.x;
    const int wid = tid >> 5;
    const int lane = tid & 31;

    // ---- load Q tile ----
#pragma unroll
    for (int j = 0; j < 4; j++) {
        int i = tid + j * 256;
        int r = i >> 3;
        int ck = i & 7;
        size_t e = (size_t)(b * TT + qb + r) * DD + h * HD + ck * 8;
        CP16(sw128(QT, r, ck), (const char*)&g_Q[e]);
    }
    CPCOMMIT();

    auto load_kv = [&](int kt, int s) {
        const uint32_t sb = STG0 + s * FSTAGE_B;
#pragma unroll
        for (int j = 0; j < 2; j++) {
            int i = tid + j * 256;
            int r = i >> 3;
            int ck = i & 7;
            size_t e = (size_t)(b * TT + kt * 64 + r) * DKV + kvh * HD + ck * 8;
            uint32_t so = sw128(sb, r, ck);
            CP16(so,           (const char*)&g_K[e]);
            CP16(so + KVSUB_B, (const char*)&g_V[e]);
        }
    };

    const int NT = 2 * (qt + 1);

    load_kv(0, 0); CPCOMMIT();
    if (NT > 1) { load_kv(1, 1); CPCOMMIT(); }

    CPWAIT(2);
    __syncthreads();

    // ---- Q fragments (register-resident) ----
    uint32_t qF[4][4];
    {
        int ar = lane & 15;
        int ac = lane >> 4;
#pragma unroll
        for (int ks = 0; ks < 4; ks++) {
            uint32_t ad = sw128(QT, wid * 16 + ar, 2 * ks + ac);
            LDSM4(qF[ks][0], qF[ks][1], qF[ks][2], qF[ks][3], ad);
        }
    }

    float oacc[8][4];
#pragma unroll
    for (int i = 0; i < 8; i++)
#pragma unroll
        for (int q = 0; q < 4; q++) oacc[i][q] = 0.f;
    float mrow[2] = {-1e30f, -1e30f};
    float lrow[2] = {0.f, 0.f};

    const int wr = qb + wid * 16;
    const float scale = 0.125f;

    for (int kt = 0; kt < NT; kt++) {
        const int s = kt % FSTAGES;
        const int kb = kt * 64;

        CPWAIT(1);
        __syncthreads();

        if (kt + 2 < NT) {
            load_kv(kt + 2, (kt + 2) % FSTAGES);
            CPCOMMIT();
        }

        const uint32_t KH = STG0 + s * FSTAGE_B;
        const uint32_t VH = KH + KVSUB_B;

        // ---- S = Q K^T (1-pass fp16) ----
        float sacc[8][4];
#pragma unroll
        for (int i = 0; i < 8; i++)
#pragma unroll
            for (int q = 0; q < 4; q++) sacc[i][q] = 0.f;

        {
            int br = lane & 7;
            int bsel = lane >> 4;
            int bksel = (lane >> 3) & 1;
#pragma unroll
            for (int ks = 0; ks < 4; ks++) {
                int bc = 2 * ks + bksel;
#pragma unroll
                for (int fp = 0; fp < 4; fp++) {
                    int krow = fp * 16 + bsel * 8 + br;
                    uint32_t t0, t1, t2, t3;
                    LDSM4(t0, t1, t2, t3, sw128(KH, krow, bc));
                    MMAH16816R(sacc[2 * fp],     qF[ks], t0, t1);
                    MMAH16816R(sacc[2 * fp + 1], qF[ks], t2, t3);
                }
            }
        }

        // ---- scale + causal mask ----
        const bool need_mask = (kb + 63 > wr);
#pragma unroll
        for (int fn = 0; fn < 8; fn++)
#pragma unroll
            for (int q = 0; q < 4; q++) sacc[fn][q] *= scale;
        if (need_mask) {
#pragma unroll
            for (int fn = 0; fn < 8; fn++)
#pragma unroll
                for (int q = 0; q < 4; q++) {
                    int kc = kb + fn * 8 + (lane & 3) * 2 + (q & 1);
                    int qr = wr + (lane >> 2) + (q >> 1) * 8;
                    if (kc > qr) sacc[fn][q] = -1e30f;
                }
        }

        // ---- online softmax ----
#pragma unroll
        for (int r = 0; r < 2; r++) {
            float rmax = -1e30f;
#pragma unroll
            for (int fn = 0; fn < 8; fn++) {
                rmax = fmaxf(rmax, sacc[fn][2 * r]);
                rmax = fmaxf(rmax, sacc[fn][2 * r + 1]);
            }
            rmax = fmaxf(rmax, __shfl_xor_sync(0xffffffffu, rmax, 1));
            rmax = fmaxf(rmax, __shfl_xor_sync(0xffffffffu, rmax, 2));

            float mn = fmaxf(mrow[r], rmax);
            float alpha = __expf(mrow[r] - mn);
            mrow[r] = mn;

            float rs = 0.f;
#pragma unroll
            for (int fn = 0; fn < 8; fn++) {
                float p0 = __expf(sacc[fn][2 * r] - mn);
                float p1 = __expf(sacc[fn][2 * r + 1] - mn);
                sacc[fn][2 * r] = p0;
                sacc[fn][2 * r + 1] = p1;
                rs += p0 + p1;
            }
            rs += __shfl_xor_sync(0xffffffffu, rs, 1);
            rs += __shfl_xor_sync(0xffffffffu, rs, 2);
            lrow[r] = lrow[r] * alpha + rs;

#pragma unroll
            for (int fn = 0; fn < 8; fn++) {
                oacc[fn][2 * r]     *= alpha;
                oacc[fn][2 * r + 1] *= alpha;
            }
        }

        // ---- O += P V (P single fp16, V single) ----
        {
            int g = lane >> 3;
            int vr_off = (g & 1) * 8 + (lane & 7);
            int vc_off = g >> 1;
#pragma unroll
            for (int ks = 0; ks < 4; ks++) {
                uint32_t pF[4];
                pF[0] = pack_h2(sacc[2 * ks][0],     sacc[2 * ks][1]);
                pF[1] = pack_h2(sacc[2 * ks][2],     sacc[2 * ks][3]);
                pF[2] = pack_h2(sacc[2 * ks + 1][0], sacc[2 * ks + 1][1]);
                pF[3] = pack_h2(sacc[2 * ks + 1][2], sacc[2 * ks + 1][3]);

                int vrow = ks * 16 + vr_off;
#pragma unroll
                for (int fv = 0; fv < 4; fv++) {
                    int vchunk = 2 * fv + vc_off;
                    uint32_t t0, t1, t2, t3;
                    LDSM4T(t0, t1, t2, t3, sw128(VH, vrow, vchunk));
                    MMAH16816R(oacc[2 * fv],     pF, t0, t1);
                    MMAH16816R(oacc[2 * fv + 1], pF, t2, t3);
                }
            }
        }
    }

    // ---- epilogue: normalize, fp16 store ----
#pragma unroll
    for (int r = 0; r < 2; r++) {
        float inv = 1.f / lrow[r];
        int row = wr + (lane >> 2) + 8 * r;
#pragma unroll
        for (int fn = 0; fn < 8; fn++) {
            int col = h * HD + fn * 8 + (lane & 3) * 2;
            float x0 = oacc[fn][2 * r] * inv;
            float x1 = oacc[fn][2 * r + 1] * inv;
            size_t e = (size_t)(b * TT + row) * DD + col;
            *(uint32_t*)&g_A[e] = pack_h2(x0, x1);
        }
    }
}

// ---------------------------------------------------------------------------
// Launch
// ---------------------------------------------------------------------------
extern "C" void kernel_launch(void* const* d_in, const int* in_sizes, int n_in,
                              void* d_out, int out_size)
{
    const float* x  = (const float*)d_in[0];
    const float* Wq = (const float*)d_in[1];
    const float* Wk = (const float*)d_in[2];
    const float* Wv = (const float*)d_in[3];
    const float* Wo = (const float*)d_in[4];
    float* out = (float*)d_out;

    __half *xh, *wqkv, *wo, *qh, *kh, *vh, *ah;
    cudaGetSymbolAddress((void**)&xh, g_x);
    cudaGetSymbolAddress((void**)&wqkv, g_Wqkv);
    cudaGetSymbolAddress((void**)&wo, g_Wo);
    cudaGetSymbolAddress((void**)&qh, g_Q);
    cudaGetSymbolAddress((void**)&kh, g_K);
    cudaGetSymbolAddress((void**)&vh, g_V);
    cudaGetSymbolAddress((void**)&ah, g_A);

    cudaFuncSetAttribute(gemm_tc_kernel<0>,
                         cudaFuncAttributeMaxDynamicSharedMemorySize, GEMM_SMEM);
    cudaFuncSetAttribute(gemm_tc_kernel<1>,
                         cudaFuncAttributeMaxDynamicSharedMemorySize, GEMM_SMEM);
    cudaFuncSetAttribute(flash_tc_kernel,
                         cudaFuncAttributeMaxDynamicSharedMemorySize, FLASH_SMEM);

    // fp32 -> fp16 converts
    const int n_x  = MTOT * DD / 4, n_wq = DD * DD / 4, n_wk = DKV * DD / 4;
    conv_h_kernel<<<(n_x  + 255) / 256, 256>>>(x,  xh, n_x);
    conv_h_kernel<<<(n_wq + 255) / 256, 256>>>(Wq, wqkv, n_wq);
    conv_h_kernel<<<(n_wk + 255) / 256, 256>>>(Wk, wqkv + (size_t)DD * DD, n_wk);
    conv_h_kernel<<<(n_wk + 255) / 256, 256>>>(Wv, wqkv + (size_t)(DD + DKV) * DD, n_wk);
    conv_h_kernel<<<(n_wq + 255) / 256, 256>>>(Wo, wo, n_wq);

    // Merged QKV projection (fp16 1-pass)
    gemm_tc_kernel<0><<<dim3(NQKV / 128, MTOT / 128), 512, GEMM_SMEM>>>(
        xh, wqkv, nullptr, qh, kh, vh, MTOT, NQKV, DD);

    // fp16 1-pass causal GQA flash attention
    flash_tc_kernel<<<dim3(TT / 128, HH, BB), 256, FLASH_SMEM>>>();

    // Output projection (fp16 1-pass) -> fp32 out
    gemm_tc_kernel<1><<<dim3(DD / 128, MTOT / 128), 512, GEMM_SMEM>>>(
        ah, wo, out, nullptr, nullptr, nullptr, MTOT, DD, DD);
}

// round 11
// speedup vs baseline: 2.2047x; 1.0171x over previous
#include <cuda_runtime.h>
#include <cuda_fp16.h>
#include <cstdint>
#include <math.h>

// Problem constants
#define BB   2
#define TT   2048
#define DD   2048
#define HH   32
#define KVH  8
#define HD   64
#define MTOT (BB*TT)      // 4096
#define DKV  (KVH*HD)     // 512
#define NQKV (DD + 2*DKV) // 3072

// ---------------------------------------------------------------------------
// Scratch (__device__ globals; no allocation allowed) — all single fp16
// ---------------------------------------------------------------------------
__device__ __half g_x[(size_t)MTOT * DD];
__device__ __half g_Wqkv[(size_t)NQKV * DD];           // [Wq; Wk; Wv]
__device__ __half g_Wo[(size_t)DD * DD];

__device__ __half g_Q[(size_t)MTOT * DD];
__device__ __half g_K[(size_t)MTOT * DKV];
__device__ __half g_V[(size_t)MTOT * DKV];
__device__ __half g_A[(size_t)MTOT * DD];

// ---------------------------------------------------------------------------
// Helpers (portable PTX only: cp.async / ldmatrix / mma.sync)
// ---------------------------------------------------------------------------
__device__ __forceinline__ uint32_t s2u(const void* p) {
    return (uint32_t)__cvta_generic_to_shared(p);
}

#define CP16(sa, ga) \
    asm volatile("cp.async.cg.shared.global [%0], [%1], 16;" :: "r"(sa), "l"(ga) : "memory")
#define CPCOMMIT()  asm volatile("cp.async.commit_group;" ::: "memory")
#define CPWAIT(n)   asm volatile("cp.async.wait_group %0;" :: "n"(n) : "memory")

#define LDSM4(r0, r1, r2, r3, addr) \
    asm volatile("ldmatrix.sync.aligned.m8n8.x4.shared.b16 {%0,%1,%2,%3}, [%4];" \
        : "=r"(r0), "=r"(r1), "=r"(r2), "=r"(r3) : "r"(addr))

#define LDSM4T(r0, r1, r2, r3, addr) \
    asm volatile("ldmatrix.sync.aligned.m8n8.x4.trans.shared.b16 {%0,%1,%2,%3}, [%4];" \
        : "=r"(r0), "=r"(r1), "=r"(r2), "=r"(r3) : "r"(addr))

// fp16 mma, b from array
#define MMAH16816(d, a, b) \
    asm volatile("mma.sync.aligned.m16n8k16.row.col.f32.f16.f16.f32 " \
        "{%0,%1,%2,%3}, {%4,%5,%6,%7}, {%8,%9}, {%0,%1,%2,%3};" \
        : "+f"((d)[0]), "+f"((d)[1]), "+f"((d)[2]), "+f"((d)[3]) \
        : "r"((a)[0]), "r"((a)[1]), "r"((a)[2]), "r"((a)[3]), "r"((b)[0]), "r"((b)[1]))

// fp16 mma, b from scalars
#define MMAH16816R(d, a, b0v, b1v) \
    asm volatile("mma.sync.aligned.m16n8k16.row.col.f32.f16.f16.f32 " \
        "{%0,%1,%2,%3}, {%4,%5,%6,%7}, {%8,%9}, {%0,%1,%2,%3};" \
        : "+f"((d)[0]), "+f"((d)[1]), "+f"((d)[2]), "+f"((d)[3]) \
        : "r"((a)[0]), "r"((a)[1]), "r"((a)[2]), "r"((a)[3]), "r"(b0v), "r"(b1v))

// 128B-row swizzle (all tiles now 128B rows)
__device__ __forceinline__ uint32_t sw128(uint32_t base, int row, int chunk) {
    return base + row * 128 + ((chunk ^ (row & 7)) << 4);
}

__device__ __forceinline__ uint32_t pack_h2(float x0, float x1) {
    __half2 p = __halves2half2(__float2half_rn(x0), __float2half_rn(x1));
    return *(uint32_t*)&p;
}

// ---------------------------------------------------------------------------
// Merged fp32 -> fp16 convert kernel: all 5 regions in one launch.
// Region quads: x=2M, Wq=1M, Wk=256K, Wv=256K, Wo=1M  (total 4718592)
// ---------------------------------------------------------------------------
#define NQ_X  (MTOT * DD / 4)
#define NQ_WQ (DD * DD / 4)
#define NQ_WK (DKV * DD / 4)
#define NQ_ALL (NQ_X + NQ_WQ + 2 * NQ_WK + NQ_WQ)

__global__ __launch_bounds__(256)
void conv_all_kernel(const float* __restrict__ x,  const float* __restrict__ Wq,
                     const float* __restrict__ Wk, const float* __restrict__ Wv,
                     const float* __restrict__ Wo,
                     __half* __restrict__ xh, __half* __restrict__ wqkv,
                     __half* __restrict__ wo)
{
    int i = blockIdx.x * blockDim.x + threadIdx.x;
    if (i >= NQ_ALL) return;
    const float* src;
    __half* dst;
    int j = i;
    if (j < NQ_X)                 { src = x;  dst = xh; }
    else if ((j -= NQ_X) < NQ_WQ) { src = Wq; dst = wqkv; }
    else if ((j -= NQ_WQ) < NQ_WK){ src = Wk; dst = wqkv + (size_t)DD * DD; }
    else if ((j -= NQ_WK) < NQ_WK){ src = Wv; dst = wqkv + (size_t)(DD + DKV) * DD; }
    else { j -= NQ_WK;             src = Wo; dst = wo; }
    float4 v = ((const float4*)src)[j];
    ((uint2*)dst)[j] = make_uint2(pack_h2(v.x, v.y), pack_h2(v.z, v.w));
}

// ---------------------------------------------------------------------------
// fp16 1-pass GEMM:  C = A * B^T
// CTA 128x128, BK=64 (128B rows, sw128), 3-stage cp.async (96KB),
// one __syncthreads per 64-K chunk. 512 threads = 16 warps (4x4), warp 32x32.
// MODE 0: QKV epilogue (Q/K/V fp16 to separate buffers); MODE 1: fp32 C
// ---------------------------------------------------------------------------
#define GSTAGES   3
#define GTILE_B   16384                     // 128 rows x 128 B
#define GSTAGE_B  (2 * GTILE_B)             // 32 KB
#define GEMM_SMEM (GSTAGES * GSTAGE_B)      // 96 KB

template<int MODE>
__global__ __launch_bounds__(512)
void gemm_tc_kernel(const __half* __restrict__ Ah, const __half* __restrict__ Bh,
                    float* __restrict__ C,
                    __half* __restrict__ Qo, __half* __restrict__ Ko, __half* __restrict__ Vo,
                    int M, int N, int K)
{
    extern __shared__ __align__(128) char smem[];
    const uint32_t sbase = s2u(smem);

    const int tid = threadIdx.x;
    const int wid = tid >> 5;
    const int lane = tid & 31;
    const int bm = blockIdx.y * 128;
    const int bn = blockIdx.x * 128;

    const int wm = (wid & 3) * 32;
    const int wn = (wid >> 2) * 32;

    const size_t rowstride = (size_t)K * 2;
    const int NC = K >> 6;                  // K / 64

    auto load_chunk = [&](int c, int s) {
        const uint32_t sb = sbase + s * GSTAGE_B;
        const size_t k0b = (size_t)c * 128; // 64 halves = 128 bytes
#pragma unroll
        for (int t = 0; t < 2; t++) {
            const int rbase = t ? bn : bm;
            const char* src = (const char*)(t ? Bh : Ah);
#pragma unroll
            for (int j = 0; j < 2; j++) {
                int i = tid + j * 512;      // 0..1023
                int r = i >> 3;             // row 0..127
                int ck = i & 7;             // 16B chunk
                const char* ga = src + (size_t)(rbase + r) * rowstride + k0b + ck * 16;
                CP16(sw128(sb + t * GTILE_B, r, ck), ga);
            }
        }
    };

    float acc[2][4][4];
#pragma unroll
    for (int i = 0; i < 2; i++)
#pragma unroll
        for (int j = 0; j < 4; j++)
#pragma unroll
            for (int q = 0; q < 4; q++) acc[i][j][q] = 0.f;

    // prefill 2 stages (NC = 32 always here)
    load_chunk(0, 0); CPCOMMIT();
    load_chunk(1, 1); CPCOMMIT();

    for (int c = 0; c < NC; c++) {
        const int s = c % GSTAGES;
        CPWAIT(1);                 // chunk c resident (pending: c+1)
        __syncthreads();           // single barrier per chunk

        if (c + 2 < NC) {          // overwrites stage (c-1)%3 — reads closed pre-barrier
            load_chunk(c + 2, (c + 2) % GSTAGES);
            CPCOMMIT();
        }

        const uint32_t sA = sbase + s * GSTAGE_B;
        const uint32_t sB = sA + GTILE_B;

#pragma unroll
        for (int ks = 0; ks < 4; ks++) {    // four k16 steps per BK=64
            uint32_t af[2][4], bf[4][2];
            {
                int ar = (lane & 15);
                int ac = 2 * ks + (lane >> 4);
#pragma unroll
                for (int fm = 0; fm < 2; fm++) {
                    uint32_t ad = sw128(sA, wm + fm * 16 + ar, ac);
                    LDSM4(af[fm][0], af[fm][1], af[fm][2], af[fm][3], ad);
                }
                int br = (lane & 7);
                int bsel = (lane >> 4);
                int bc = 2 * ks + ((lane >> 3) & 1);
#pragma unroll
                for (int fp = 0; fp < 2; fp++) {
                    uint32_t bd = sw128(sB, wn + (fp * 2 + bsel) * 8 + br, bc);
                    uint32_t t0, t1, t2, t3;
                    LDSM4(t0, t1, t2, t3, bd);
                    bf[fp * 2][0] = t0; bf[fp * 2][1] = t1;
                    bf[fp * 2 + 1][0] = t2; bf[fp * 2 + 1][1] = t3;
                }
            }

#pragma unroll
            for (int fm = 0; fm < 2; fm++)
#pragma unroll
                for (int fn = 0; fn < 4; fn++)
                    MMAH16816(acc[fm][fn], af[fm], bf[fn]);
        }
    }

    const int lr = lane >> 2;
    const int lc = (lane & 3) * 2;
#pragma unroll
    for (int fm = 0; fm < 2; fm++) {
#pragma unroll
        for (int fn = 0; fn < 4; fn++) {
            int r0 = bm + wm + fm * 16 + lr;
            int cc = bn + wn + fn * 8 + lc;
            if (MODE == 0) {
                if (bn < DD) {
                    *(uint32_t*)&Qo[(size_t)r0 * DD + cc] =
                        pack_h2(acc[fm][fn][0], acc[fm][fn][1]);
                    *(uint32_t*)&Qo[(size_t)(r0 + 8) * DD + cc] =
                        pack_h2(acc[fm][fn][2], acc[fm][fn][3]);
                } else if (bn < DD + DKV) {
                    int kc = cc - DD;
                    *(uint32_t*)&Ko[(size_t)r0 * DKV + kc] =
                        pack_h2(acc[fm][fn][0], acc[fm][fn][1]);
                    *(uint32_t*)&Ko[(size_t)(r0 + 8) * DKV + kc] =
                        pack_h2(acc[fm][fn][2], acc[fm][fn][3]);
                } else {
                    int vc = cc - DD - DKV;
                    *(uint32_t*)&Vo[(size_t)r0 * DKV + vc] =
                        pack_h2(acc[fm][fn][0], acc[fm][fn][1]);
                    *(uint32_t*)&Vo[(size_t)(r0 + 8) * DKV + vc] =
                        pack_h2(acc[fm][fn][2], acc[fm][fn][3]);
                }
            } else {
                *(float2*)&C[(size_t)r0 * N + cc]       = make_float2(acc[fm][fn][0], acc[fm][fn][1]);
                *(float2*)&C[(size_t)(r0 + 8) * N + cc] = make_float2(acc[fm][fn][2], acc[fm][fn][3]);
            }
        }
    }
}

// ---------------------------------------------------------------------------
// Tensor-core flash attention (fp16 1-pass) — unchanged from R10.
// Grid (T/128, H, B), 256 threads = 8 warps x 16 q-rows.
// KV tile 64 (K+V fp16, 16KB/stage), 3-stage cp.async ring.
// SMEM: Q 16KB + 3 x 16KB = 64KB.
// ---------------------------------------------------------------------------
#define QTILE_B   16384
#define KVSUB_B   8192
#define FSTAGE_B  (2 * KVSUB_B)
#define FSTAGES   3
#define FLASH_SMEM (QTILE_B + FSTAGES * FSTAGE_B)

__global__ __launch_bounds__(256, 1)
void flash_tc_kernel()
{
    extern __shared__ __align__(128) char fsm[];
    const uint32_t sbase = s2u(fsm);
    const uint32_t QT = sbase;
    const uint32_t STG0 = sbase + QTILE_B;

    const int qt  = blockIdx.x;
    const int h   = blockIdx.y;
    const int b   = blockIdx.z;
    const int kvh = h >> 2;
    const int qb  = qt * 128;

    const int tid = threadIdx.x;
    const int wid = tid >> 5;
    const int lane = tid & 31;

    // ---- load Q tile ----
#pragma unroll
    for (int j = 0; j < 4; j++) {
        int i = tid + j * 256;
        int r = i >> 3;
        int ck = i & 7;
        size_t e = (size_t)(b * TT + qb + r) * DD + h * HD + ck * 8;
        CP16(sw128(QT, r, ck), (const char*)&g_Q[e]);
    }
    CPCOMMIT();

    auto load_kv = [&](int kt, int s) {
        const uint32_t sb = STG0 + s * FSTAGE_B;
#pragma unroll
        for (int j = 0; j < 2; j++) {
            int i = tid + j * 256;
            int r = i >> 3;
            int ck = i & 7;
            size_t e = (size_t)(b * TT + kt * 64 + r) * DKV + kvh * HD + ck * 8;
            uint32_t so = sw128(sb, r, ck);
            CP16(so,           (const char*)&g_K[e]);
            CP16(so + KVSUB_B, (const char*)&g_V[e]);
        }
    };

    const int NT = 2 * (qt + 1);

    load_kv(0, 0); CPCOMMIT();
    if (NT > 1) { load_kv(1, 1); CPCOMMIT(); }

    CPWAIT(2);
    __syncthreads();

    // ---- Q fragments (register-resident) ----
    uint32_t qF[4][4];
    {
        int ar = lane & 15;
        int ac = lane >> 4;
#pragma unroll
        for (int ks = 0; ks < 4; ks++) {
            uint32_t ad = sw128(QT, wid * 16 + ar, 2 * ks + ac);
            LDSM4(qF[ks][0], qF[ks][1], qF[ks][2], qF[ks][3], ad);
        }
    }

    float oacc[8][4];
#pragma unroll
    for (int i = 0; i < 8; i++)
#pragma unroll
        for (int q = 0; q < 4; q++) oacc[i][q] = 0.f;
    float mrow[2] = {-1e30f, -1e30f};
    float lrow[2] = {0.f, 0.f};

    const int wr = qb + wid * 16;
    const float scale = 0.125f;

    for (int kt = 0; kt < NT; kt++) {
        const int s = kt % FSTAGES;
        const int kb = kt * 64;

        CPWAIT(1);
        __syncthreads();

        if (kt + 2 < NT) {
            load_kv(kt + 2, (kt + 2) % FSTAGES);
            CPCOMMIT();
        }

        const uint32_t KH = STG0 + s * FSTAGE_B;
        const uint32_t VH = KH + KVSUB_B;

        // ---- S = Q K^T ----
        float sacc[8][4];
#pragma unroll
        for (int i = 0; i < 8; i++)
#pragma unroll
            for (int q = 0; q < 4; q++) sacc[i][q] = 0.f;

        {
            int br = lane & 7;
            int bsel = lane >> 4;
            int bksel = (lane >> 3) & 1;
#pragma unroll
            for (int ks = 0; ks < 4; ks++) {
                int bc = 2 * ks + bksel;
#pragma unroll
                for (int fp = 0; fp < 4; fp++) {
                    int krow = fp * 16 + bsel * 8 + br;
                    uint32_t t0, t1, t2, t3;
                    LDSM4(t0, t1, t2, t3, sw128(KH, krow, bc));
                    MMAH16816R(sacc[2 * fp],     qF[ks], t0, t1);
                    MMAH16816R(sacc[2 * fp + 1], qF[ks], t2, t3);
                }
            }
        }

        // ---- scale + causal mask ----
        const bool need_mask = (kb + 63 > wr);
#pragma unroll
        for (int fn = 0; fn < 8; fn++)
#pragma unroll
            for (int q = 0; q < 4; q++) sacc[fn][q] *= scale;
        if (need_mask) {
#pragma unroll
            for (int fn = 0; fn < 8; fn++)
#pragma unroll
                for (int q = 0; q < 4; q++) {
                    int kc = kb + fn * 8 + (lane & 3) * 2 + (q & 1);
                    int qr = wr + (lane >> 2) + (q >> 1) * 8;
                    if (kc > qr) sacc[fn][q] = -1e30f;
                }
        }

        // ---- online softmax ----
#pragma unroll
        for (int r = 0; r < 2; r++) {
            float rmax = -1e30f;
#pragma unroll
            for (int fn = 0; fn < 8; fn++) {
                rmax = fmaxf(rmax, sacc[fn][2 * r]);
                rmax = fmaxf(rmax, sacc[fn][2 * r + 1]);
            }
            rmax = fmaxf(rmax, __shfl_xor_sync(0xffffffffu, rmax, 1));
            rmax = fmaxf(rmax, __shfl_xor_sync(0xffffffffu, rmax, 2));

            float mn = fmaxf(mrow[r], rmax);
            float alpha = __expf(mrow[r] - mn);
            mrow[r] = mn;

            float rs = 0.f;
#pragma unroll
            for (int fn = 0; fn < 8; fn++) {
                float p0 = __expf(sacc[fn][2 * r] - mn);
                float p1 = __expf(sacc[fn][2 * r + 1] - mn);
                sacc[fn][2 * r] = p0;
                sacc[fn][2 * r + 1] = p1;
                rs += p0 + p1;
            }
            rs += __shfl_xor_sync(0xffffffffu, rs, 1);
            rs += __shfl_xor_sync(0xffffffffu, rs, 2);
            lrow[r] = lrow[r] * alpha + rs;

#pragma unroll
            for (int fn = 0; fn < 8; fn++) {
                oacc[fn][2 * r]     *= alpha;
                oacc[fn][2 * r + 1] *= alpha;
            }
        }

        // ---- O += P V ----
        {
            int g = lane >> 3;
            int vr_off = (g & 1) * 8 + (lane & 7);
            int vc_off = g >> 1;
#pragma unroll
            for (int ks = 0; ks < 4; ks++) {
                uint32_t pF[4];
                pF[0] = pack_h2(sacc[2 * ks][0],     sacc[2 * ks][1]);
                pF[1] = pack_h2(sacc[2 * ks][2],     sacc[2 * ks][3]);
                pF[2] = pack_h2(sacc[2 * ks + 1][0], sacc[2 * ks + 1][1]);
                pF[3] = pack_h2(sacc[2 * ks + 1][2], sacc[2 * ks + 1][3]);

                int vrow = ks * 16 + vr_off;
#pragma unroll
                for (int fv = 0; fv < 4; fv++) {
                    int vchunk = 2 * fv + vc_off;
                    uint32_t t0, t1, t2, t3;
                    LDSM4T(t0, t1, t2, t3, sw128(VH, vrow, vchunk));
                    MMAH16816R(oacc[2 * fv],     pF, t0, t1);
                    MMAH16816R(oacc[2 * fv + 1], pF, t2, t3);
                }
            }
        }
    }

    // ---- epilogue: normalize, fp16 store ----
#pragma unroll
    for (int r = 0; r < 2; r++) {
        float inv = 1.f / lrow[r];
        int row = wr + (lane >> 2) + 8 * r;
#pragma unroll
        for (int fn = 0; fn < 8; fn++) {
            int col = h * HD + fn * 8 + (lane & 3) * 2;
            float x0 = oacc[fn][2 * r] * inv;
            float x1 = oacc[fn][2 * r + 1] * inv;
            size_t e = (size_t)(b * TT + row) * DD + col;
            *(uint32_t*)&g_A[e] = pack_h2(x0, x1);
        }
    }
}

// ---------------------------------------------------------------------------
// Launch
// ---------------------------------------------------------------------------
extern "C" void kernel_launch(void* const* d_in, const int* in_sizes, int n_in,
                              void* d_out, int out_size)
{
    const float* x  = (const float*)d_in[0];
    const float* Wq = (const float*)d_in[1];
    const float* Wk = (const float*)d_in[2];
    const float* Wv = (const float*)d_in[3];
    const float* Wo = (const float*)d_in[4];
    float* out = (float*)d_out;

    __half *xh, *wqkv, *wo, *qh, *kh, *vh, *ah;
    cudaGetSymbolAddress((void**)&xh, g_x);
    cudaGetSymbolAddress((void**)&wqkv, g_Wqkv);
    cudaGetSymbolAddress((void**)&wo, g_Wo);
    cudaGetSymbolAddress((void**)&qh, g_Q);
    cudaGetSymbolAddress((void**)&kh, g_K);
    cudaGetSymbolAddress((void**)&vh, g_V);
    cudaGetSymbolAddress((void**)&ah, g_A);

    cudaFuncSetAttribute(gemm_tc_kernel<0>,
                         cudaFuncAttributeMaxDynamicSharedMemorySize, GEMM_SMEM);
    cudaFuncSetAttribute(gemm_tc_kernel<1>,
                         cudaFuncAttributeMaxDynamicSharedMemorySize, GEMM_SMEM);
    cudaFuncSetAttribute(flash_tc_kernel,
                         cudaFuncAttributeMaxDynamicSharedMemorySize, FLASH_SMEM);

    // Merged fp32 -> fp16 converts (one launch)
    conv_all_kernel<<<(NQ_ALL + 255) / 256, 256>>>(x, Wq, Wk, Wv, Wo, xh, wqkv, wo);

    // Merged QKV projection (fp16 1-pass, BK=64)
    gemm_tc_kernel<0><<<dim3(NQKV / 128, MTOT / 128), 512, GEMM_SMEM>>>(
        xh, wqkv, nullptr, qh, kh, vh, MTOT, NQKV, DD);

    // fp16 1-pass causal GQA flash attention
    flash_tc_kernel<<<dim3(TT / 128, HH, BB), 256, FLASH_SMEM>>>();

    // Output projection (fp16 1-pass, BK=64) -> fp32 out
    gemm_tc_kernel<1><<<dim3(DD / 128, MTOT / 128), 512, GEMM_SMEM>>>(
        ah, wo, out, nullptr, nullptr, nullptr, MTOT, DD, DD);
}

// round 12
// speedup vs baseline: 2.4707x; 1.1207x over previous
#include <cuda_runtime.h>
#include <cuda_fp16.h>
#include <cstdint>
#include <math.h>

// Problem constants
#define BB   2
#define TT   2048
#define DD   2048
#define HH   32
#define KVH  8
#define HD   64
#define MTOT (BB*TT)      // 4096
#define DKV  (KVH*HD)     // 512
#define NQKV (DD + 2*DKV) // 3072

// ---------------------------------------------------------------------------
// Scratch (__device__ globals; no allocation allowed) — all single fp16
// ---------------------------------------------------------------------------
__device__ __half g_x[(size_t)MTOT * DD];
__device__ __half g_Wqkv[(size_t)NQKV * DD];           // [Wq; Wk; Wv]
__device__ __half g_Wo[(size_t)DD * DD];

__device__ __half g_Q[(size_t)MTOT * DD];
__device__ __half g_K[(size_t)MTOT * DKV];
__device__ __half g_V[(size_t)MTOT * DKV];
__device__ __half g_A[(size_t)MTOT * DD];

// ---------------------------------------------------------------------------
// Helpers (portable PTX only: cp.async / ldmatrix / mma.sync)
// ---------------------------------------------------------------------------
__device__ __forceinline__ uint32_t s2u(const void* p) {
    return (uint32_t)__cvta_generic_to_shared(p);
}

#define CP16(sa, ga) \
    asm volatile("cp.async.cg.shared.global [%0], [%1], 16;" :: "r"(sa), "l"(ga) : "memory")
#define CPCOMMIT()  asm volatile("cp.async.commit_group;" ::: "memory")
#define CPWAIT(n)   asm volatile("cp.async.wait_group %0;" :: "n"(n) : "memory")

#define LDSM4(r0, r1, r2, r3, addr) \
    asm volatile("ldmatrix.sync.aligned.m8n8.x4.shared.b16 {%0,%1,%2,%3}, [%4];" \
        : "=r"(r0), "=r"(r1), "=r"(r2), "=r"(r3) : "r"(addr))

#define LDSM4T(r0, r1, r2, r3, addr) \
    asm volatile("ldmatrix.sync.aligned.m8n8.x4.trans.shared.b16 {%0,%1,%2,%3}, [%4];" \
        : "=r"(r0), "=r"(r1), "=r"(r2), "=r"(r3) : "r"(addr))

// fp16 mma, b from array
#define MMAH16816(d, a, b) \
    asm volatile("mma.sync.aligned.m16n8k16.row.col.f32.f16.f16.f32 " \
        "{%0,%1,%2,%3}, {%4,%5,%6,%7}, {%8,%9}, {%0,%1,%2,%3};" \
        : "+f"((d)[0]), "+f"((d)[1]), "+f"((d)[2]), "+f"((d)[3]) \
        : "r"((a)[0]), "r"((a)[1]), "r"((a)[2]), "r"((a)[3]), "r"((b)[0]), "r"((b)[1]))

// fp16 mma, b from scalars
#define MMAH16816R(d, a, b0v, b1v) \
    asm volatile("mma.sync.aligned.m16n8k16.row.col.f32.f16.f16.f32 " \
        "{%0,%1,%2,%3}, {%4,%5,%6,%7}, {%8,%9}, {%0,%1,%2,%3};" \
        : "+f"((d)[0]), "+f"((d)[1]), "+f"((d)[2]), "+f"((d)[3]) \
        : "r"((a)[0]), "r"((a)[1]), "r"((a)[2]), "r"((a)[3]), "r"(b0v), "r"(b1v))

// 128B-row swizzle
__device__ __forceinline__ uint32_t sw128(uint32_t base, int row, int chunk) {
    return base + row * 128 + ((chunk ^ (row & 7)) << 4);
}

__device__ __forceinline__ uint32_t pack_h2(float x0, float x1) {
    __half2 p = __halves2half2(__float2half_rn(x0), __float2half_rn(x1));
    return *(uint32_t*)&p;
}

// ---------------------------------------------------------------------------
// Merged fp32 -> fp16 convert kernel: all 5 regions in one launch.
// ---------------------------------------------------------------------------
#define NQ_X  (MTOT * DD / 4)
#define NQ_WQ (DD * DD / 4)
#define NQ_WK (DKV * DD / 4)
#define NQ_ALL (NQ_X + NQ_WQ + 2 * NQ_WK + NQ_WQ)

__global__ __launch_bounds__(256)
void conv_all_kernel(const float* __restrict__ x,  const float* __restrict__ Wq,
                     const float* __restrict__ Wk, const float* __restrict__ Wv,
                     const float* __restrict__ Wo,
                     __half* __restrict__ xh, __half* __restrict__ wqkv,
                     __half* __restrict__ wo)
{
    int i = blockIdx.x * blockDim.x + threadIdx.x;
    if (i >= NQ_ALL) return;
    const float* src;
    __half* dst;
    int j = i;
    if (j < NQ_X)                 { src = x;  dst = xh; }
    else if ((j -= NQ_X) < NQ_WQ) { src = Wq; dst = wqkv; }
    else if ((j -= NQ_WQ) < NQ_WK){ src = Wk; dst = wqkv + (size_t)DD * DD; }
    else if ((j -= NQ_WK) < NQ_WK){ src = Wv; dst = wqkv + (size_t)(DD + DKV) * DD; }
    else { j -= NQ_WK;             src = Wo; dst = wo; }
    float4 v = ((const float4*)src)[j];
    ((uint2*)dst)[j] = make_uint2(pack_h2(v.x, v.y), pack_h2(v.z, v.w));
}

// ---------------------------------------------------------------------------
// fp16 1-pass GEMM:  C = A * B^T
// CTA 128x128, BK=64, 3-stage cp.async (96KB), one barrier per chunk.
// 512 threads = 16 warps (4x4), warp tile 32x32.
// __launch_bounds__(512, 2): cap regs at 64 so 2 CTAs co-reside per SM.
// ---------------------------------------------------------------------------
#define GSTAGES   3
#define GTILE_B   16384
#define GSTAGE_B  (2 * GTILE_B)             // 32 KB
#define GEMM_SMEM (GSTAGES * GSTAGE_B)      // 96 KB

template<int MODE>
__global__ __launch_bounds__(512, 2)
void gemm_tc_kernel(const __half* __restrict__ Ah, const __half* __restrict__ Bh,
                    float* __restrict__ C,
                    __half* __restrict__ Qo, __half* __restrict__ Ko, __half* __restrict__ Vo,
                    int M, int N, int K)
{
    extern __shared__ __align__(128) char smem[];
    const uint32_t sbase = s2u(smem);

    const int tid = threadIdx.x;
    const int wid = tid >> 5;
    const int lane = tid & 31;
    const int bm = blockIdx.y * 128;
    const int bn = blockIdx.x * 128;

    const int wm = (wid & 3) * 32;
    const int wn = (wid >> 2) * 32;

    const size_t rowstride = (size_t)K * 2;
    const int NC = K >> 6;

    auto load_chunk = [&](int c, int s) {
        const uint32_t sb = sbase + s * GSTAGE_B;
        const size_t k0b = (size_t)c * 128;
#pragma unroll
        for (int t = 0; t < 2; t++) {
            const int rbase = t ? bn : bm;
            const char* src = (const char*)(t ? Bh : Ah);
#pragma unroll
            for (int j = 0; j < 2; j++) {
                int i = tid + j * 512;
                int r = i >> 3;
                int ck = i & 7;
                const char* ga = src + (size_t)(rbase + r) * rowstride + k0b + ck * 16;
                CP16(sw128(sb + t * GTILE_B, r, ck), ga);
            }
        }
    };

    float acc[2][4][4];
#pragma unroll
    for (int i = 0; i < 2; i++)
#pragma unroll
        for (int j = 0; j < 4; j++)
#pragma unroll
            for (int q = 0; q < 4; q++) acc[i][j][q] = 0.f;

    load_chunk(0, 0); CPCOMMIT();
    load_chunk(1, 1); CPCOMMIT();

    for (int c = 0; c < NC; c++) {
        const int s = c % GSTAGES;
        CPWAIT(1);
        __syncthreads();

        if (c + 2 < NC) {
            load_chunk(c + 2, (c + 2) % GSTAGES);
            CPCOMMIT();
        }

        const uint32_t sA = sbase + s * GSTAGE_B;
        const uint32_t sB = sA + GTILE_B;

#pragma unroll
        for (int ks = 0; ks < 4; ks++) {
            uint32_t af[2][4], bf[4][2];
            {
                int ar = (lane & 15);
                int ac = 2 * ks + (lane >> 4);
#pragma unroll
                for (int fm = 0; fm < 2; fm++) {
                    uint32_t ad = sw128(sA, wm + fm * 16 + ar, ac);
                    LDSM4(af[fm][0], af[fm][1], af[fm][2], af[fm][3], ad);
                }
                int br = (lane & 7);
                int bsel = (lane >> 4);
                int bc = 2 * ks + ((lane >> 3) & 1);
#pragma unroll
                for (int fp = 0; fp < 2; fp++) {
                    uint32_t bd = sw128(sB, wn + (fp * 2 + bsel) * 8 + br, bc);
                    uint32_t t0, t1, t2, t3;
                    LDSM4(t0, t1, t2, t3, bd);
                    bf[fp * 2][0] = t0; bf[fp * 2][1] = t1;
                    bf[fp * 2 + 1][0] = t2; bf[fp * 2 + 1][1] = t3;
                }
            }

#pragma unroll
            for (int fm = 0; fm < 2; fm++)
#pragma unroll
                for (int fn = 0; fn < 4; fn++)
                    MMAH16816(acc[fm][fn], af[fm], bf[fn]);
        }
    }

    const int lr = lane >> 2;
    const int lc = (lane & 3) * 2;
#pragma unroll
    for (int fm = 0; fm < 2; fm++) {
#pragma unroll
        for (int fn = 0; fn < 4; fn++) {
            int r0 = bm + wm + fm * 16 + lr;
            int cc = bn + wn + fn * 8 + lc;
            if (MODE == 0) {
                if (bn < DD) {
                    *(uint32_t*)&Qo[(size_t)r0 * DD + cc] =
                        pack_h2(acc[fm][fn][0], acc[fm][fn][1]);
                    *(uint32_t*)&Qo[(size_t)(r0 + 8) * DD + cc] =
                        pack_h2(acc[fm][fn][2], acc[fm][fn][3]);
                } else if (bn < DD + DKV) {
                    int kc = cc - DD;
                    *(uint32_t*)&Ko[(size_t)r0 * DKV + kc] =
                        pack_h2(acc[fm][fn][0], acc[fm][fn][1]);
                    *(uint32_t*)&Ko[(size_t)(r0 + 8) * DKV + kc] =
                        pack_h2(acc[fm][fn][2], acc[fm][fn][3]);
                } else {
                    int vc = cc - DD - DKV;
                    *(uint32_t*)&Vo[(size_t)r0 * DKV + vc] =
                        pack_h2(acc[fm][fn][0], acc[fm][fn][1]);
                    *(uint32_t*)&Vo[(size_t)(r0 + 8) * DKV + vc] =
                        pack_h2(acc[fm][fn][2], acc[fm][fn][3]);
                }
            } else {
                *(float2*)&C[(size_t)r0 * N + cc]       = make_float2(acc[fm][fn][0], acc[fm][fn][1]);
                *(float2*)&C[(size_t)(r0 + 8) * N + cc] = make_float2(acc[fm][fn][2], acc[fm][fn][3]);
            }
        }
    }
}

// ---------------------------------------------------------------------------
// Tensor-core flash attention (fp16 1-pass).
// __launch_bounds__(256, 2): cap regs at 128 so 2 CTAs co-reside per SM.
// Grid (T/128, H, B), 256 threads = 8 warps x 16 q-rows.
// KV tile 64 (K+V fp16, 16KB/stage), 3-stage cp.async ring. SMEM 64KB.
// ---------------------------------------------------------------------------
#define QTILE_B   16384
#define KVSUB_B   8192
#define FSTAGE_B  (2 * KVSUB_B)
#define FSTAGES   3
#define FLASH_SMEM (QTILE_B + FSTAGES * FSTAGE_B)

__global__ __launch_bounds__(256, 2)
void flash_tc_kernel()
{
    extern __shared__ __align__(128) char fsm[];
    const uint32_t sbase = s2u(fsm);
    const uint32_t QT = sbase;
    const uint32_t STG0 = sbase + QTILE_B;

    const int qt  = blockIdx.x;
    const int h   = blockIdx.y;
    const int b   = blockIdx.z;
    const int kvh = h >> 2;
    const int qb  = qt * 128;

    const int tid = threadIdx.x;
    const int wid = tid >> 5;
    const int lane = tid & 31;

    // ---- load Q tile ----
#pragma unroll
    for (int j = 0; j < 4; j++) {
        int i = tid + j * 256;
        int r = i >> 3;
        int ck = i & 7;
        size_t e = (size_t)(b * TT + qb + r) * DD + h * HD + ck * 8;
        CP16(sw128(QT, r, ck), (const char*)&g_Q[e]);
    }
    CPCOMMIT();

    auto load_kv = [&](int kt, int s) {
        const uint32_t sb = STG0 + s * FSTAGE_B;
#pragma unroll
        for (int j = 0; j < 2; j++) {
            int i = tid + j * 256;
            int r = i >> 3;
            int ck = i & 7;
            size_t e = (size_t)(b * TT + kt * 64 + r) * DKV + kvh * HD + ck * 8;
            uint32_t so = sw128(sb, r, ck);
            CP16(so,           (const char*)&g_K[e]);
            CP16(so + KVSUB_B, (const char*)&g_V[e]);
        }
    };

    const int NT = 2 * (qt + 1);

    load_kv(0, 0); CPCOMMIT();
    if (NT > 1) { load_kv(1, 1); CPCOMMIT(); }

    CPWAIT(2);
    __syncthreads();

    // ---- Q fragments (register-resident) ----
    uint32_t qF[4][4];
    {
        int ar = lane & 15;
        int ac = lane >> 4;
#pragma unroll
        for (int ks = 0; ks < 4; ks++) {
            uint32_t ad = sw128(QT, wid * 16 + ar, 2 * ks + ac);
            LDSM4(qF[ks][0], qF[ks][1], qF[ks][2], qF[ks][3], ad);
        }
    }

    float oacc[8][4];
#pragma unroll
    for (int i = 0; i < 8; i++)
#pragma unroll
        for (int q = 0; q < 4; q++) oacc[i][q] = 0.f;
    float mrow[2] = {-1e30f, -1e30f};
    float lrow[2] = {0.f, 0.f};

    const int wr = qb + wid * 16;
    const float scale = 0.125f;

    for (int kt = 0; kt < NT; kt++) {
        const int s = kt % FSTAGES;
        const int kb = kt * 64;

        CPWAIT(1);
        __syncthreads();

        if (kt + 2 < NT) {
            load_kv(kt + 2, (kt + 2) % FSTAGES);
            CPCOMMIT();
        }

        const uint32_t KH = STG0 + s * FSTAGE_B;
        const uint32_t VH = KH + KVSUB_B;

        // ---- S = Q K^T ----
        float sacc[8][4];
#pragma unroll
        for (int i = 0; i < 8; i++)
#pragma unroll
            for (int q = 0; q < 4; q++) sacc[i][q] = 0.f;

        {
            int br = lane & 7;
            int bsel = lane >> 4;
            int bksel = (lane >> 3) & 1;
#pragma unroll
            for (int ks = 0; ks < 4; ks++) {
                int bc = 2 * ks + bksel;
#pragma unroll
                for (int fp = 0; fp < 4; fp++) {
                    int krow = fp * 16 + bsel * 8 + br;
                    uint32_t t0, t1, t2, t3;
                    LDSM4(t0, t1, t2, t3, sw128(KH, krow, bc));
                    MMAH16816R(sacc[2 * fp],     qF[ks], t0, t1);
                    MMAH16816R(sacc[2 * fp + 1], qF[ks], t2, t3);
                }
            }
        }

        // ---- scale + causal mask ----
        const bool need_mask = (kb + 63 > wr);
#pragma unroll
        for (int fn = 0; fn < 8; fn++)
#pragma unroll
            for (int q = 0; q < 4; q++) sacc[fn][q] *= scale;
        if (need_mask) {
#pragma unroll
            for (int fn = 0; fn < 8; fn++)
#pragma unroll
                for (int q = 0; q < 4; q++) {
                    int kc = kb + fn * 8 + (lane & 3) * 2 + (q & 1);
                    int qr = wr + (lane >> 2) + (q >> 1) * 8;
                    if (kc > qr) sacc[fn][q] = -1e30f;
                }
        }

        // ---- online softmax ----
#pragma unroll
        for (int r = 0; r < 2; r++) {
            float rmax = -1e30f;
#pragma unroll
            for (int fn = 0; fn < 8; fn++) {
                rmax = fmaxf(rmax, sacc[fn][2 * r]);
                rmax = fmaxf(rmax, sacc[fn][2 * r + 1]);
            }
            rmax = fmaxf(rmax, __shfl_xor_sync(0xffffffffu, rmax, 1));
            rmax = fmaxf(rmax, __shfl_xor_sync(0xffffffffu, rmax, 2));

            float mn = fmaxf(mrow[r], rmax);
            float alpha = __expf(mrow[r] - mn);
            mrow[r] = mn;

            float rs = 0.f;
#pragma unroll
            for (int fn = 0; fn < 8; fn++) {
                float p0 = __expf(sacc[fn][2 * r] - mn);
                float p1 = __expf(sacc[fn][2 * r + 1] - mn);
                sacc[fn][2 * r] = p0;
                sacc[fn][2 * r + 1] = p1;
                rs += p0 + p1;
            }
            rs += __shfl_xor_sync(0xffffffffu, rs, 1);
            rs += __shfl_xor_sync(0xffffffffu, rs, 2);
            lrow[r] = lrow[r] * alpha + rs;

#pragma unroll
            for (int fn = 0; fn < 8; fn++) {
                oacc[fn][2 * r]     *= alpha;
                oacc[fn][2 * r + 1] *= alpha;
            }
        }

        // ---- O += P V ----
        {
            int g = lane >> 3;
            int vr_off = (g & 1) * 8 + (lane & 7);
            int vc_off = g >> 1;
#pragma unroll
            for (int ks = 0; ks < 4; ks++) {
                uint32_t pF[4];
                pF[0] = pack_h2(sacc[2 * ks][0],     sacc[2 * ks][1]);
                pF[1] = pack_h2(sacc[2 * ks][2],     sacc[2 * ks][3]);
                pF[2] = pack_h2(sacc[2 * ks + 1][0], sacc[2 * ks + 1][1]);
                pF[3] = pack_h2(sacc[2 * ks + 1][2], sacc[2 * ks + 1][3]);

                int vrow = ks * 16 + vr_off;
#pragma unroll
                for (int fv = 0; fv < 4; fv++) {
                    int vchunk = 2 * fv + vc_off;
                    uint32_t t0, t1, t2, t3;
                    LDSM4T(t0, t1, t2, t3, sw128(VH, vrow, vchunk));
                    MMAH16816R(oacc[2 * fv],     pF, t0, t1);
                    MMAH16816R(oacc[2 * fv + 1], pF, t2, t3);
                }
            }
        }
    }

    // ---- epilogue: normalize, fp16 store ----
#pragma unroll
    for (int r = 0; r < 2; r++) {
        float inv = 1.f / lrow[r];
        int row = wr + (lane >> 2) + 8 * r;
#pragma unroll
        for (int fn = 0; fn < 8; fn++) {
            int col = h * HD + fn * 8 + (lane & 3) * 2;
            float x0 = oacc[fn][2 * r] * inv;
            float x1 = oacc[fn][2 * r + 1] * inv;
            size_t e = (size_t)(b * TT + row) * DD + col;
            *(uint32_t*)&g_A[e] = pack_h2(x0, x1);
        }
    }
}

// ---------------------------------------------------------------------------
// Launch
// ---------------------------------------------------------------------------
extern "C" void kernel_launch(void* const* d_in, const int* in_sizes, int n_in,
                              void* d_out, int out_size)
{
    const float* x  = (const float*)d_in[0];
    const float* Wq = (const float*)d_in[1];
    const float* Wk = (const float*)d_in[2];
    const float* Wv = (const float*)d_in[3];
    const float* Wo = (const float*)d_in[4];
    float* out = (float*)d_out;

    __half *xh, *wqkv, *wo, *qh, *kh, *vh, *ah;
    cudaGetSymbolAddress((void**)&xh, g_x);
    cudaGetSymbolAddress((void**)&wqkv, g_Wqkv);
    cudaGetSymbolAddress((void**)&wo, g_Wo);
    cudaGetSymbolAddress((void**)&qh, g_Q);
    cudaGetSymbolAddress((void**)&kh, g_K);
    cudaGetSymbolAddress((void**)&vh, g_V);
    cudaGetSymbolAddress((void**)&ah, g_A);

    cudaFuncSetAttribute(gemm_tc_kernel<0>,
                         cudaFuncAttributeMaxDynamicSharedMemorySize, GEMM_SMEM);
    cudaFuncSetAttribute(gemm_tc_kernel<1>,
                         cudaFuncAttributeMaxDynamicSharedMemorySize, GEMM_SMEM);
    cudaFuncSetAttribute(flash_tc_kernel,
                         cudaFuncAttributeMaxDynamicSharedMemorySize, FLASH_SMEM);

    // Merged fp32 -> fp16 converts (one launch)
    conv_all_kernel<<<(NQ_ALL + 255) / 256, 256>>>(x, Wq, Wk, Wv, Wo, xh, wqkv, wo);

    // Merged QKV projection (fp16 1-pass, BK=64, 2 CTAs/SM)
    gemm_tc_kernel<0><<<dim3(NQKV / 128, MTOT / 128), 512, GEMM_SMEM>>>(
        xh, wqkv, nullptr, qh, kh, vh, MTOT, NQKV, DD);

    // fp16 1-pass causal GQA flash attention (2 CTAs/SM)
    flash_tc_kernel<<<dim3(TT / 128, HH, BB), 256, FLASH_SMEM>>>();

    // Output projection (fp16 1-pass, BK=64, 2 CTAs/SM) -> fp32 out
    gemm_tc_kernel<1><<<dim3(DD / 128, MTOT / 128), 512, GEMM_SMEM>>>(
        ah, wo, out, nullptr, nullptr, nullptr, MTOT, DD, DD);
}

// round 13
// speedup vs baseline: 2.6650x; 1.0786x over previous
#include <cuda_runtime.h>
#include <cuda_fp16.h>
#include <cstdint>
#include <math.h>

// Problem constants
#define BB   2
#define TT   2048
#define DD   2048
#define HH   32
#define KVH  8
#define HD   64
#define MTOT (BB*TT)      // 4096
#define DKV  (KVH*HD)     // 512
#define NQKV (DD + 2*DKV) // 3072

// ---------------------------------------------------------------------------
// Scratch (__device__ globals; no allocation allowed) — all single fp16
// ---------------------------------------------------------------------------
__device__ __half g_x[(size_t)MTOT * DD];
__device__ __half g_Wqkv[(size_t)NQKV * DD];           // [Wq; Wk; Wv]
__device__ __half g_Wo[(size_t)DD * DD];

__device__ __half g_Q[(size_t)MTOT * DD];
__device__ __half g_K[(size_t)MTOT * DKV];
__device__ __half g_V[(size_t)MTOT * DKV];
__device__ __half g_A[(size_t)MTOT * DD];

// ---------------------------------------------------------------------------
// Helpers (portable PTX only: cp.async / ldmatrix / mma.sync)
// ---------------------------------------------------------------------------
__device__ __forceinline__ uint32_t s2u(const void* p) {
    return (uint32_t)__cvta_generic_to_shared(p);
}

#define CP16(sa, ga) \
    asm volatile("cp.async.cg.shared.global [%0], [%1], 16;" :: "r"(sa), "l"(ga) : "memory")
#define CPCOMMIT()  asm volatile("cp.async.commit_group;" ::: "memory")
#define CPWAIT(n)   asm volatile("cp.async.wait_group %0;" :: "n"(n) : "memory")

#define LDSM4(r0, r1, r2, r3, addr) \
    asm volatile("ldmatrix.sync.aligned.m8n8.x4.shared.b16 {%0,%1,%2,%3}, [%4];" \
        : "=r"(r0), "=r"(r1), "=r"(r2), "=r"(r3) : "r"(addr))

#define LDSM4T(r0, r1, r2, r3, addr) \
    asm volatile("ldmatrix.sync.aligned.m8n8.x4.trans.shared.b16 {%0,%1,%2,%3}, [%4];" \
        : "=r"(r0), "=r"(r1), "=r"(r2), "=r"(r3) : "r"(addr))

// fp16 mma, b from array
#define MMAH16816(d, a, b) \
    asm volatile("mma.sync.aligned.m16n8k16.row.col.f32.f16.f16.f32 " \
        "{%0,%1,%2,%3}, {%4,%5,%6,%7}, {%8,%9}, {%0,%1,%2,%3};" \
        : "+f"((d)[0]), "+f"((d)[1]), "+f"((d)[2]), "+f"((d)[3]) \
        : "r"((a)[0]), "r"((a)[1]), "r"((a)[2]), "r"((a)[3]), "r"((b)[0]), "r"((b)[1]))

// fp16 mma, b from scalars
#define MMAH16816R(d, a, b0v, b1v) \
    asm volatile("mma.sync.aligned.m16n8k16.row.col.f32.f16.f16.f32 " \
        "{%0,%1,%2,%3}, {%4,%5,%6,%7}, {%8,%9}, {%0,%1,%2,%3};" \
        : "+f"((d)[0]), "+f"((d)[1]), "+f"((d)[2]), "+f"((d)[3]) \
        : "r"((a)[0]), "r"((a)[1]), "r"((a)[2]), "r"((a)[3]), "r"(b0v), "r"(b1v))

// 128B-row swizzle
__device__ __forceinline__ uint32_t sw128(uint32_t base, int row, int chunk) {
    return base + row * 128 + ((chunk ^ (row & 7)) << 4);
}

__device__ __forceinline__ uint32_t pack_h2(float x0, float x1) {
    __half2 p = __halves2half2(__float2half_rn(x0), __float2half_rn(x1));
    return *(uint32_t*)&p;
}

// ---------------------------------------------------------------------------
// Merged fp32 -> fp16 convert kernel: all 5 regions in one launch.
// ---------------------------------------------------------------------------
#define NQ_X  (MTOT * DD / 4)
#define NQ_WQ (DD * DD / 4)
#define NQ_WK (DKV * DD / 4)
#define NQ_ALL (NQ_X + NQ_WQ + 2 * NQ_WK + NQ_WQ)

__global__ __launch_bounds__(256)
void conv_all_kernel(const float* __restrict__ x,  const float* __restrict__ Wq,
                     const float* __restrict__ Wk, const float* __restrict__ Wv,
                     const float* __restrict__ Wo,
                     __half* __restrict__ xh, __half* __restrict__ wqkv,
                     __half* __restrict__ wo)
{
    int i = blockIdx.x * blockDim.x + threadIdx.x;
    if (i >= NQ_ALL) return;
    const float* src;
    __half* dst;
    int j = i;
    if (j < NQ_X)                 { src = x;  dst = xh; }
    else if ((j -= NQ_X) < NQ_WQ) { src = Wq; dst = wqkv; }
    else if ((j -= NQ_WQ) < NQ_WK){ src = Wk; dst = wqkv + (size_t)DD * DD; }
    else if ((j -= NQ_WK) < NQ_WK){ src = Wv; dst = wqkv + (size_t)(DD + DKV) * DD; }
    else { j -= NQ_WK;             src = Wo; dst = wo; }
    float4 v = ((const float4*)src)[j];
    ((uint2*)dst)[j] = make_uint2(pack_h2(v.x, v.y), pack_h2(v.z, v.w));
}

// ---------------------------------------------------------------------------
// fp16 1-pass GEMM:  C = A * B^T
// CTA 128x128, BK=64, 3-stage cp.async (96KB), one barrier per chunk.
// 256 threads = 8 warps (2x4), warp tile 64x32 (fm=4, fn=4).
// __launch_bounds__(256, 2): 128-reg cap, 2 CTAs/SM.
// ---------------------------------------------------------------------------
#define GSTAGES   3
#define GTILE_B   16384
#define GSTAGE_B  (2 * GTILE_B)             // 32 KB
#define GEMM_SMEM (GSTAGES * GSTAGE_B)      // 96 KB

template<int MODE>
__global__ __launch_bounds__(256, 2)
void gemm_tc_kernel(const __half* __restrict__ Ah, const __half* __restrict__ Bh,
                    float* __restrict__ C,
                    __half* __restrict__ Qo, __half* __restrict__ Ko, __half* __restrict__ Vo,
                    int M, int N, int K)
{
    extern __shared__ __align__(128) char smem[];
    const uint32_t sbase = s2u(smem);

    const int tid = threadIdx.x;
    const int wid = tid >> 5;
    const int lane = tid & 31;
    const int bm = blockIdx.y * 128;
    const int bn = blockIdx.x * 128;

    const int wm = (wid & 1) * 64;      // 2 warps in M (64 rows each)
    const int wn = (wid >> 1) * 32;     // 4 warps in N (32 cols each)

    const size_t rowstride = (size_t)K * 2;
    const int NC = K >> 6;

    auto load_chunk = [&](int c, int s) {
        const uint32_t sb = sbase + s * GSTAGE_B;
        const size_t k0b = (size_t)c * 128;
#pragma unroll
        for (int t = 0; t < 2; t++) {
            const int rbase = t ? bn : bm;
            const char* src = (const char*)(t ? Bh : Ah);
#pragma unroll
            for (int j = 0; j < 4; j++) {
                int i = tid + j * 256;      // 0..1023
                int r = i >> 3;
                int ck = i & 7;
                const char* ga = src + (size_t)(rbase + r) * rowstride + k0b + ck * 16;
                CP16(sw128(sb + t * GTILE_B, r, ck), ga);
            }
        }
    };

    float acc[4][4][4];
#pragma unroll
    for (int i = 0; i < 4; i++)
#pragma unroll
        for (int j = 0; j < 4; j++)
#pragma unroll
            for (int q = 0; q < 4; q++) acc[i][j][q] = 0.f;

    load_chunk(0, 0); CPCOMMIT();
    load_chunk(1, 1); CPCOMMIT();

    for (int c = 0; c < NC; c++) {
        const int s = c % GSTAGES;
        CPWAIT(1);
        __syncthreads();

        if (c + 2 < NC) {
            load_chunk(c + 2, (c + 2) % GSTAGES);
            CPCOMMIT();
        }

        const uint32_t sA = sbase + s * GSTAGE_B;
        const uint32_t sB = sA + GTILE_B;

#pragma unroll
        for (int ks = 0; ks < 4; ks++) {
            uint32_t af[4][4], bf[4][2];
            {
                int ar = (lane & 15);
                int ac = 2 * ks + (lane >> 4);
#pragma unroll
                for (int fm = 0; fm < 4; fm++) {
                    uint32_t ad = sw128(sA, wm + fm * 16 + ar, ac);
                    LDSM4(af[fm][0], af[fm][1], af[fm][2], af[fm][3], ad);
                }
                int br = (lane & 7);
                int bsel = (lane >> 4);
                int bc = 2 * ks + ((lane >> 3) & 1);
#pragma unroll
                for (int fp = 0; fp < 2; fp++) {
                    uint32_t bd = sw128(sB, wn + (fp * 2 + bsel) * 8 + br, bc);
                    uint32_t t0, t1, t2, t3;
                    LDSM4(t0, t1, t2, t3, bd);
                    bf[fp * 2][0] = t0; bf[fp * 2][1] = t1;
                    bf[fp * 2 + 1][0] = t2; bf[fp * 2 + 1][1] = t3;
                }
            }

#pragma unroll
            for (int fm = 0; fm < 4; fm++)
#pragma unroll
                for (int fn = 0; fn < 4; fn++)
                    MMAH16816(acc[fm][fn], af[fm], bf[fn]);
        }
    }

    const int lr = lane >> 2;
    const int lc = (lane & 3) * 2;
#pragma unroll
    for (int fm = 0; fm < 4; fm++) {
#pragma unroll
        for (int fn = 0; fn < 4; fn++) {
            int r0 = bm + wm + fm * 16 + lr;
            int cc = bn + wn + fn * 8 + lc;
            if (MODE == 0) {
                if (bn < DD) {
                    *(uint32_t*)&Qo[(size_t)r0 * DD + cc] =
                        pack_h2(acc[fm][fn][0], acc[fm][fn][1]);
                    *(uint32_t*)&Qo[(size_t)(r0 + 8) * DD + cc] =
                        pack_h2(acc[fm][fn][2], acc[fm][fn][3]);
                } else if (bn < DD + DKV) {
                    int kc = cc - DD;
                    *(uint32_t*)&Ko[(size_t)r0 * DKV + kc] =
                        pack_h2(acc[fm][fn][0], acc[fm][fn][1]);
                    *(uint32_t*)&Ko[(size_t)(r0 + 8) * DKV + kc] =
                        pack_h2(acc[fm][fn][2], acc[fm][fn][3]);
                } else {
                    int vc = cc - DD - DKV;
                    *(uint32_t*)&Vo[(size_t)r0 * DKV + vc] =
                        pack_h2(acc[fm][fn][0], acc[fm][fn][1]);
                    *(uint32_t*)&Vo[(size_t)(r0 + 8) * DKV + vc] =
                        pack_h2(acc[fm][fn][2], acc[fm][fn][3]);
                }
            } else {
                *(float2*)&C[(size_t)r0 * N + cc]       = make_float2(acc[fm][fn][0], acc[fm][fn][1]);
                *(float2*)&C[(size_t)(r0 + 8) * N + cc] = make_float2(acc[fm][fn][2], acc[fm][fn][3]);
            }
        }
    }
}

// ---------------------------------------------------------------------------
// Tensor-core flash attention (fp16 1-pass) — unchanged from R12.
// __launch_bounds__(256, 2). Grid (T/128, H, B), 8 warps x 16 q-rows.
// KV tile 64, 3-stage cp.async ring. SMEM 64KB.
// ---------------------------------------------------------------------------
#define QTILE_B   16384
#define KVSUB_B   8192
#define FSTAGE_B  (2 * KVSUB_B)
#define FSTAGES   3
#define FLASH_SMEM (QTILE_B + FSTAGES * FSTAGE_B)

__global__ __launch_bounds__(256, 2)
void flash_tc_kernel()
{
    extern __shared__ __align__(128) char fsm[];
    const uint32_t sbase = s2u(fsm);
    const uint32_t QT = sbase;
    const uint32_t STG0 = sbase + QTILE_B;

    const int qt  = blockIdx.x;
    const int h   = blockIdx.y;
    const int b   = blockIdx.z;
    const int kvh = h >> 2;
    const int qb  = qt * 128;

    const int tid = threadIdx.x;
    const int wid = tid >> 5;
    const int lane = tid & 31;

    // ---- load Q tile ----
#pragma unroll
    for (int j = 0; j < 4; j++) {
        int i = tid + j * 256;
        int r = i >> 3;
        int ck = i & 7;
        size_t e = (size_t)(b * TT + qb + r) * DD + h * HD + ck * 8;
        CP16(sw128(QT, r, ck), (const char*)&g_Q[e]);
    }
    CPCOMMIT();

    auto load_kv = [&](int kt, int s) {
        const uint32_t sb = STG0 + s * FSTAGE_B;
#pragma unroll
        for (int j = 0; j < 2; j++) {
            int i = tid + j * 256;
            int r = i >> 3;
            int ck = i & 7;
            size_t e = (size_t)(b * TT + kt * 64 + r) * DKV + kvh * HD + ck * 8;
            uint32_t so = sw128(sb, r, ck);
            CP16(so,           (const char*)&g_K[e]);
            CP16(so + KVSUB_B, (const char*)&g_V[e]);
        }
    };

    const int NT = 2 * (qt + 1);

    load_kv(0, 0); CPCOMMIT();
    if (NT > 1) { load_kv(1, 1); CPCOMMIT(); }

    CPWAIT(2);
    __syncthreads();

    // ---- Q fragments (register-resident) ----
    uint32_t qF[4][4];
    {
        int ar = lane & 15;
        int ac = lane >> 4;
#pragma unroll
        for (int ks = 0; ks < 4; ks++) {
            uint32_t ad = sw128(QT, wid * 16 + ar, 2 * ks + ac);
            LDSM4(qF[ks][0], qF[ks][1], qF[ks][2], qF[ks][3], ad);
        }
    }

    float oacc[8][4];
#pragma unroll
    for (int i = 0; i < 8; i++)
#pragma unroll
        for (int q = 0; q < 4; q++) oacc[i][q] = 0.f;
    float mrow[2] = {-1e30f, -1e30f};
    float lrow[2] = {0.f, 0.f};

    const int wr = qb + wid * 16;
    const float scale = 0.125f;

    for (int kt = 0; kt < NT; kt++) {
        const int s = kt % FSTAGES;
        const int kb = kt * 64;

        CPWAIT(1);
        __syncthreads();

        if (kt + 2 < NT) {
            load_kv(kt + 2, (kt + 2) % FSTAGES);
            CPCOMMIT();
        }

        const uint32_t KH = STG0 + s * FSTAGE_B;
        const uint32_t VH = KH + KVSUB_B;

        // ---- S = Q K^T ----
        float sacc[8][4];
#pragma unroll
        for (int i = 0; i < 8; i++)
#pragma unroll
            for (int q = 0; q < 4; q++) sacc[i][q] = 0.f;

        {
            int br = lane & 7;
            int bsel = lane >> 4;
            int bksel = (lane >> 3) & 1;
#pragma unroll
            for (int ks = 0; ks < 4; ks++) {
                int bc = 2 * ks + bksel;
#pragma unroll
                for (int fp = 0; fp < 4; fp++) {
                    int krow = fp * 16 + bsel * 8 + br;
                    uint32_t t0, t1, t2, t3;
                    LDSM4(t0, t1, t2, t3, sw128(KH, krow, bc));
                    MMAH16816R(sacc[2 * fp],     qF[ks], t0, t1);
                    MMAH16816R(sacc[2 * fp + 1], qF[ks], t2, t3);
                }
            }
        }

        // ---- scale + causal mask ----
        const bool need_mask = (kb + 63 > wr);
#pragma unroll
        for (int fn = 0; fn < 8; fn++)
#pragma unroll
            for (int q = 0; q < 4; q++) sacc[fn][q] *= scale;
        if (need_mask) {
#pragma unroll
            for (int fn = 0; fn < 8; fn++)
#pragma unroll
                for (int q = 0; q < 4; q++) {
                    int kc = kb + fn * 8 + (lane & 3) * 2 + (q & 1);
                    int qr = wr + (lane >> 2) + (q >> 1) * 8;
                    if (kc > qr) sacc[fn][q] = -1e30f;
                }
        }

        // ---- online softmax ----
#pragma unroll
        for (int r = 0; r < 2; r++) {
            float rmax = -1e30f;
#pragma unroll
            for (int fn = 0; fn < 8; fn++) {
                rmax = fmaxf(rmax, sacc[fn][2 * r]);
                rmax = fmaxf(rmax, sacc[fn][2 * r + 1]);
            }
            rmax = fmaxf(rmax, __shfl_xor_sync(0xffffffffu, rmax, 1));
            rmax = fmaxf(rmax, __shfl_xor_sync(0xffffffffu, rmax, 2));

            float mn = fmaxf(mrow[r], rmax);
            float alpha = __expf(mrow[r] - mn);
            mrow[r] = mn;

            float rs = 0.f;
#pragma unroll
            for (int fn = 0; fn < 8; fn++) {
                float p0 = __expf(sacc[fn][2 * r] - mn);
                float p1 = __expf(sacc[fn][2 * r + 1] - mn);
                sacc[fn][2 * r] = p0;
                sacc[fn][2 * r + 1] = p1;
                rs += p0 + p1;
            }
            rs += __shfl_xor_sync(0xffffffffu, rs, 1);
            rs += __shfl_xor_sync(0xffffffffu, rs, 2);
            lrow[r] = lrow[r] * alpha + rs;

#pragma unroll
            for (int fn = 0; fn < 8; fn++) {
                oacc[fn][2 * r]     *= alpha;
                oacc[fn][2 * r + 1] *= alpha;
            }
        }

        // ---- O += P V ----
        {
            int g = lane >> 3;
            int vr_off = (g & 1) * 8 + (lane & 7);
            int vc_off = g >> 1;
#pragma unroll
            for (int ks = 0; ks < 4; ks++) {
                uint32_t pF[4];
                pF[0] = pack_h2(sacc[2 * ks][0],     sacc[2 * ks][1]);
                pF[1] = pack_h2(sacc[2 * ks][2],     sacc[2 * ks][3]);
                pF[2] = pack_h2(sacc[2 * ks + 1][0], sacc[2 * ks + 1][1]);
                pF[3] = pack_h2(sacc[2 * ks + 1][2], sacc[2 * ks + 1][3]);

                int vrow = ks * 16 + vr_off;
#pragma unroll
                for (int fv = 0; fv < 4; fv++) {
                    int vchunk = 2 * fv + vc_off;
                    uint32_t t0, t1, t2, t3;
                    LDSM4T(t0, t1, t2, t3, sw128(VH, vrow, vchunk));
                    MMAH16816R(oacc[2 * fv],     pF, t0, t1);
                    MMAH16816R(oacc[2 * fv + 1], pF, t2, t3);
                }
            }
        }
    }

    // ---- epilogue: normalize, fp16 store ----
#pragma unroll
    for (int r = 0; r < 2; r++) {
        float inv = 1.f / lrow[r];
        int row = wr + (lane >> 2) + 8 * r;
#pragma unroll
        for (int fn = 0; fn < 8; fn++) {
            int col = h * HD + fn * 8 + (lane & 3) * 2;
            float x0 = oacc[fn][2 * r] * inv;
            float x1 = oacc[fn][2 * r + 1] * inv;
            size_t e = (size_t)(b * TT + row) * DD + col;
            *(uint32_t*)&g_A[e] = pack_h2(x0, x1);
        }
    }
}

// ---------------------------------------------------------------------------
// Launch
// ---------------------------------------------------------------------------
extern "C" void kernel_launch(void* const* d_in, const int* in_sizes, int n_in,
                              void* d_out, int out_size)
{
    const float* x  = (const float*)d_in[0];
    const float* Wq = (const float*)d_in[1];
    const float* Wk = (const float*)d_in[2];
    const float* Wv = (const float*)d_in[3];
    const float* Wo = (const float*)d_in[4];
    float* out = (float*)d_out;

    __half *xh, *wqkv, *wo, *qh, *kh, *vh, *ah;
    cudaGetSymbolAddress((void**)&xh, g_x);
    cudaGetSymbolAddress((void**)&wqkv, g_Wqkv);
    cudaGetSymbolAddress((void**)&wo, g_Wo);
    cudaGetSymbolAddress((void**)&qh, g_Q);
    cudaGetSymbolAddress((void**)&kh, g_K);
    cudaGetSymbolAddress((void**)&vh, g_V);
    cudaGetSymbolAddress((void**)&ah, g_A);

    cudaFuncSetAttribute(gemm_tc_kernel<0>,
                         cudaFuncAttributeMaxDynamicSharedMemorySize, GEMM_SMEM);
    cudaFuncSetAttribute(gemm_tc_kernel<1>,
                         cudaFuncAttributeMaxDynamicSharedMemorySize, GEMM_SMEM);
    cudaFuncSetAttribute(flash_tc_kernel,
                         cudaFuncAttributeMaxDynamicSharedMemorySize, FLASH_SMEM);

    // Merged fp32 -> fp16 converts (one launch)
    conv_all_kernel<<<(NQ_ALL + 255) / 256, 256>>>(x, Wq, Wk, Wv, Wo, xh, wqkv, wo);

    // Merged QKV projection (fp16 1-pass, BK=64, 64x32 warp tiles, 2 CTAs/SM)
    gemm_tc_kernel<0><<<dim3(NQKV / 128, MTOT / 128), 256, GEMM_SMEM>>>(
        xh, wqkv, nullptr, qh, kh, vh, MTOT, NQKV, DD);

    // fp16 1-pass causal GQA flash attention (2 CTAs/SM)
    flash_tc_kernel<<<dim3(TT / 128, HH, BB), 256, FLASH_SMEM>>>();

    // Output projection (fp16 1-pass, BK=64, 64x32 warp tiles, 2 CTAs/SM)
    gemm_tc_kernel<1><<<dim3(DD / 128, MTOT / 128), 256, GEMM_SMEM>>>(
        ah, wo, out, nullptr, nullptr, nullptr, MTOT, DD, DD);
}